// round 13
// baseline (speedup 1.0000x reference)
#include <cuda_runtime.h>
#include <cuda_bf16.h>
#include <cuda_fp16.h>
#include <math.h>
#include <stdint.h>

#define BB 8
#define SS 2048
#define DD 256
#define RR (BB*SS)          // 16384 rows total
#define NEG_INF -1.0e30f

// ----- HMMA sim tiling -----
#define TS2 128
#define NT2 (SS/TS2)                 // 16
#define TRI2 (NT2*(NT2+1)/2)         // 136
#define KC 64
#define NCHUNK (DD/KC)               // 4
#define LDA 72                       // padded smem row stride (2B elems)
#define TILE_B (128*LDA*2)           // 18432 bytes per operand tile
#define SIM_STAGE_B (2*TILE_B)       // A+B per stage = 36864
#define SIM_SMEM (2*SIM_STAGE_B)     // 73728 (covers key buffer 128*132*4=67584)

#define NCAND 10                     // merge width (rescored exactly)
#define ACAP 96                      // adjacency list capacity per row

// ----- HMMA out tiling -----
#define KF (2*DD)                    // 512
#define OUT_A_B (128*LDA*2)          // 18432
#define OUT_B_B (64*LDA*2)           // 9216
#define OUT_SMEM (2*OUT_A_B + 2*OUT_B_B)   // 55296

// ---------------- static scratch ----------------
__device__ float    g_nrm[(size_t)RR*DD];            // 16 MB exact normalized rows
__device__ __half   g_f16[(size_t)RR*DD];            // 8 MB fp16 normalized rows
__device__ uint32_t g_cand[(size_t)RR*256];          // 16.8 MB packed candidate keys
__device__ int      g_acnt[RR];                      // adjacency counts
__device__ int      g_aidx[(size_t)RR*ACAP];         // adjacency indices (batch-local)
__device__ float    g_awt[(size_t)RR*ACAP];          // adjacency weights (exact fp32)
__device__ __nv_bfloat16 g_chi[(size_t)RR*KF];       // 16 MB combined hi
__device__ __nv_bfloat16 g_clo[(size_t)RR*KF];       // 16 MB combined lo
__device__ __nv_bfloat16 g_whi[(size_t)DD*KF];       // 256 KB
__device__ __nv_bfloat16 g_wlo[(size_t)DD*KF];       // 256 KB
__device__ float    g_y[(size_t)RR*DD];              // 16 MB

__device__ __forceinline__ uint32_t smem_u32(const void* p) {
    uint32_t a;
    asm("{ .reg .u64 t; cvta.to.shared.u64 t, %1; cvt.u32.u64 %0, t; }" : "=r"(a) : "l"(p));
    return a;
}
__device__ __forceinline__ void ldmx4(uint32_t* r, uint32_t addr) {
    asm volatile("ldmatrix.sync.aligned.m8n8.x4.shared.b16 {%0,%1,%2,%3}, [%4];"
        : "=r"(r[0]), "=r"(r[1]), "=r"(r[2]), "=r"(r[3]) : "r"(addr));
}
__device__ __forceinline__ void mma16816(float* c, const uint32_t* a, uint32_t b0, uint32_t b1) {
    asm volatile("mma.sync.aligned.m16n8k16.row.col.f32.bf16.bf16.f32 "
        "{%0,%1,%2,%3}, {%4,%5,%6,%7}, {%8,%9}, {%0,%1,%2,%3};"
        : "+f"(c[0]), "+f"(c[1]), "+f"(c[2]), "+f"(c[3])
        : "r"(a[0]), "r"(a[1]), "r"(a[2]), "r"(a[3]), "r"(b0), "r"(b1));
}
__device__ __forceinline__ void mma16816h(float* c, const uint32_t* a, uint32_t b0, uint32_t b1) {
    asm volatile("mma.sync.aligned.m16n8k16.row.col.f32.f16.f16.f32 "
        "{%0,%1,%2,%3}, {%4,%5,%6,%7}, {%8,%9}, {%0,%1,%2,%3};"
        : "+f"(c[0]), "+f"(c[1]), "+f"(c[2]), "+f"(c[3])
        : "r"(a[0]), "r"(a[1]), "r"(a[2]), "r"(a[3]), "r"(b0), "r"(b1));
}
__device__ __forceinline__ void cpa16(uint32_t dst, const void* src) {
    asm volatile("cp.async.ca.shared.global [%0], [%1], 16;" :: "r"(dst), "l"(src));
}
#define CP_COMMIT() asm volatile("cp.async.commit_group;" ::: "memory")
#define CP_WAIT(n)  asm volatile("cp.async.wait_group %0;" :: "n"(n) : "memory")

// order-preserving float -> uint, top 21 bits kept, 11-bit index packed low
__device__ __forceinline__ uint32_t f2key(float f, int j) {
    uint32_t u = __float_as_uint(f);
    u ^= (uint32_t)((int)u >> 31) | 0x80000000u;
    return (u & 0xFFFFF800u) | (uint32_t)j;
}
// sorted-descending top-8 insert (guarded)
__device__ __forceinline__ void ins8(uint32_t* tk, uint32_t k) {
    if (k > tk[7]) {
        #pragma unroll
        for (int p = 7; p >= 1; p--)
            tk[p] = (k > tk[p-1]) ? tk[p-1] : (k > tk[p] ? k : tk[p]);
        if (k > tk[0]) tk[0] = k;
    }
}
// group-guarded scan of 4 packed keys
__device__ __forceinline__ void ins8x4(uint32_t* tk, uint4 kk) {
    uint32_t m0 = kk.x > kk.y ? kk.x : kk.y;
    uint32_t m1 = kk.z > kk.w ? kk.z : kk.w;
    if ((m0 > m1 ? m0 : m1) > tk[7]) {
        ins8(tk, kk.x); ins8(tk, kk.y); ins8(tk, kk.z); ins8(tk, kk.w);
    }
}

// ---------------- 0. clear adjacency counters ----------------
__global__ void k_clr() {
    int t = blockIdx.x*256 + threadIdx.x;
    if (t < RR) g_acnt[t] = 0;
}

// ---------------- 1. row L2-normalize -> fp32 + fp16; raw x -> combined[0:256] ----------------
__global__ void k_norm(const float* __restrict__ x) {
    int row = blockIdx.x;
    int t = threadIdx.x;
    float v = x[(size_t)row*DD + t];
    __shared__ float sh[8];
    float s = v*v;
    #pragma unroll
    for (int o = 16; o > 0; o >>= 1) s += __shfl_xor_sync(0xffffffffu, s, o);
    if ((t & 31) == 0) sh[t >> 5] = s;
    __syncthreads();
    if (t < 32) {
        float z = (t < 8) ? sh[t] : 0.f;
        #pragma unroll
        for (int o = 4; o > 0; o >>= 1) z += __shfl_xor_sync(0xffffffffu, z, o);
        if (t == 0) sh[0] = z;
    }
    __syncthreads();
    float nrm = sqrtf(sh[0]);
    float sc = 1.f / fmaxf(nrm, 1e-12f);
    float nv = v * sc;
    g_nrm[(size_t)row*DD + t] = nv;
    g_f16[(size_t)row*DD + t] = __float2half(nv);
    __nv_bfloat16 xh = __float2bfloat16(v);
    g_chi[(size_t)row*KF + t] = xh;
    g_clo[(size_t)row*KF + t] = __float2bfloat16(v - __bfloat162float(xh));
}

// ---------------- 1b. W hi/lo split ----------------
__global__ void k_wsplit(const float* __restrict__ W) {
    int t = blockIdx.x*256 + threadIdx.x;   // DD*KF = 131072
    float v = W[t];
    __nv_bfloat16 h = __float2bfloat16(v);
    g_whi[t] = h;
    g_wlo[t] = __float2bfloat16(v - __bfloat162float(h));
}

// ---------------- 2. sim tiles via single fp16 HMMA, cp.async 2-stage; fused top-8 candidates ----------------
__global__ void __launch_bounds__(256, 2) k_sim3() {
    extern __shared__ char smem[];
    uint32_t sb = smem_u32(smem);
    int tid = threadIdx.x;
    int lane = tid & 31, wid = tid >> 5;
    int wm = wid & 3, wn = wid >> 2;

    int t = blockIdx.x;
    int bi = 0;
    while ((bi+1)*(bi+2)/2 <= t) bi++;
    int bj = t - bi*(bi+1)/2;           // bi >= bj
    int b = blockIdx.y;
    int rA = bi*TS2, rB = bj*TS2;

    const __half* hb = g_f16 + (size_t)b*SS*DD;

    float acc[2][8][4];
    #pragma unroll
    for (int i = 0; i < 2; i++)
        #pragma unroll
        for (int j = 0; j < 8; j++)
            #pragma unroll
            for (int q = 0; q < 4; q++) acc[i][j][q] = 0.f;

    int ar = lane & 15, aseg = lane >> 4;
    int br = lane & 7, bsel = lane >> 3;
    int bnoff = (bsel >> 1) * 8, bkoff = (bsel & 1) * 8;

    int lrow = tid >> 1, lcol = (tid & 1) * 32;
    uint32_t so = (uint32_t)(lrow*LDA + lcol) * 2;

    // prologue: chunk 0 -> stage 0
    {
        const char* gA = (const char*)(hb + (size_t)(rA+lrow)*DD + lcol);
        const char* gB = (const char*)(hb + (size_t)(rB+lrow)*DD + lcol);
        uint32_t dA = sb + so, dB = sb + TILE_B + so;
        #pragma unroll
        for (int q = 0; q < 4; q++) { cpa16(dA + q*16, gA + q*16); cpa16(dB + q*16, gB + q*16); }
        CP_COMMIT();
    }

    for (int c = 0; c < NCHUNK; c++) {
        if (c + 1 < NCHUNK) {
            int kk = (c+1) * KC;
            int s = (c+1) & 1;
            const char* gA = (const char*)(hb + (size_t)(rA+lrow)*DD + kk + lcol);
            const char* gB = (const char*)(hb + (size_t)(rB+lrow)*DD + kk + lcol);
            uint32_t dA = sb + s*SIM_STAGE_B + so, dB = dA + TILE_B;
            #pragma unroll
            for (int q = 0; q < 4; q++) { cpa16(dA + q*16, gA + q*16); cpa16(dB + q*16, gB + q*16); }
            CP_COMMIT();
            CP_WAIT(1);
        } else {
            CP_WAIT(0);
        }
        __syncthreads();

        uint32_t stA = sb + (c & 1)*SIM_STAGE_B;
        uint32_t stB = stA + TILE_B;
        #pragma unroll
        for (int ks = 0; ks < KC/16; ks++) {
            int kb = ks * 16;
            uint32_t ah[2][4];
            #pragma unroll
            for (int mt = 0; mt < 2; mt++) {
                uint32_t ao = (uint32_t)((wm*32 + mt*16 + ar)*LDA + kb + aseg*8) * 2;
                ldmx4(ah[mt], stA + ao);
            }
            #pragma unroll
            for (int np = 0; np < 4; np++) {
                uint32_t bo = (uint32_t)((wn*64 + np*16 + bnoff + br)*LDA + kb + bkoff) * 2;
                uint32_t bh[4];
                ldmx4(bh, stB + bo);
                #pragma unroll
                for (int mt = 0; mt < 2; mt++)
                    #pragma unroll
                    for (int sub = 0; sub < 2; sub++)
                        mma16816h(acc[mt][np*2 + sub], ah[mt], bh[sub*2], bh[sub*2+1]);
            }
        }
        __syncthreads();
    }

    // -------- epilogue: pack keys, per-row/per-64-col-chunk top-8 --------
    uint32_t* Ck = (uint32_t*)smem;     // [128][132]
    int fr = lane >> 2, fc = (lane & 3) * 2;

    // orientation 1: rows in tile bi, cols in tile bj (key idx = rB + col)
    #pragma unroll
    for (int mt = 0; mt < 2; mt++) {
        #pragma unroll
        for (int nt = 0; nt < 8; nt++) {
            int r0 = wm*32 + mt*16 + fr;
            int cc = wn*64 + nt*8 + fc;
            int g0 = rA + r0, g1 = rA + r0 + 8;
            int j0 = rB + cc, j1 = rB + cc + 1;
            Ck[r0*132 + cc]       = (g0 == j0) ? 0u : f2key(acc[mt][nt][0], j0);
            Ck[r0*132 + cc+1]     = (g0 == j1) ? 0u : f2key(acc[mt][nt][1], j1);
            Ck[(r0+8)*132 + cc]   = (g1 == j0) ? 0u : f2key(acc[mt][nt][2], j0);
            Ck[(r0+8)*132 + cc+1] = (g1 == j1) ? 0u : f2key(acc[mt][nt][3], j1);
        }
    }
    __syncthreads();
    {
        int row = tid >> 1, half = tid & 1;
        const uint32_t* src = Ck + row*132 + half*64;
        uint32_t tk[8];
        #pragma unroll
        for (int p = 0; p < 8; p++) tk[p] = 0u;
        #pragma unroll 4
        for (int c4 = 0; c4 < 16; c4++)
            ins8x4(tk, *(const uint4*)(src + c4*4));
        uint32_t* dst = g_cand + ((size_t)(b*SS + rA + row))*256 + (bj*2 + half)*8;
        *(uint4*)(dst)     = make_uint4(tk[0], tk[1], tk[2], tk[3]);
        *(uint4*)(dst + 4) = make_uint4(tk[4], tk[5], tk[6], tk[7]);
    }

    if (bi != bj) {
        __syncthreads();
        // orientation 2: rows in tile bj, cols in tile bi (key idx = rA + row-of-A)
        #pragma unroll
        for (int mt = 0; mt < 2; mt++) {
            #pragma unroll
            for (int nt = 0; nt < 8; nt++) {
                int r0 = wm*32 + mt*16 + fr;
                int cc = wn*64 + nt*8 + fc;
                Ck[cc*132 + r0]       = f2key(acc[mt][nt][0], rA + r0);
                Ck[(cc+1)*132 + r0]   = f2key(acc[mt][nt][1], rA + r0);
                Ck[cc*132 + r0+8]     = f2key(acc[mt][nt][2], rA + r0 + 8);
                Ck[(cc+1)*132 + r0+8] = f2key(acc[mt][nt][3], rA + r0 + 8);
            }
        }
        __syncthreads();
        {
            int row = tid >> 1, half = tid & 1;
            const uint32_t* src = Ck + row*132 + half*64;
            uint32_t tk[8];
            #pragma unroll
            for (int p = 0; p < 8; p++) tk[p] = 0u;
            #pragma unroll 4
            for (int c4 = 0; c4 < 16; c4++)
                ins8x4(tk, *(const uint4*)(src + c4*4));
            uint32_t* dst = g_cand + ((size_t)(b*SS + rB + row))*256 + (bi*2 + half)*8;
            *(uint4*)(dst)     = make_uint4(tk[0], tk[1], tk[2], tk[3]);
            *(uint4*)(dst + 4) = make_uint4(tk[4], tk[5], tk[6], tk[7]);
        }
    }
}

// ---------------- 3. merge keys -> top-10 -> exact rescore -> top-3 -> scatter weighted edges ----------------
// grid RR/8, 256 threads, warp per row
__global__ void __launch_bounds__(256) k_mrg() {
    __shared__ int   cand[8][NCAND];
    __shared__ float ex[8][NCAND];
    int tid = threadIdx.x;
    int lane = tid & 31, wid = tid >> 5;
    int row = blockIdx.x*8 + wid;
    int b = row / SS;

    const uint32_t* src = g_cand + (size_t)row*256;
    uint32_t k[8];
    #pragma unroll
    for (int p = 0; p < 8; p++) k[p] = src[p*32 + lane];   // coalesced

    for (int p = 0; p < NCAND; p++) {
        uint32_t bk = 0u;
        #pragma unroll
        for (int q = 0; q < 8; q++) bk = (k[q] > bk) ? k[q] : bk;
        #pragma unroll
        for (int o = 16; o > 0; o >>= 1) {
            uint32_t ov = __shfl_xor_sync(0xffffffffu, bk, o);
            bk = (ov > bk) ? ov : bk;
        }
        #pragma unroll
        for (int q = 0; q < 8; q++) if (k[q] == bk) k[q] = 0u;   // keys unique: one holder
        if (lane == 0) cand[wid][p] = (int)(bk & 0x7FFu);
    }
    __syncwarp();

    // exact fp32 rescore
    const float* xi = g_nrm + (size_t)row*DD;
    for (int c = 0; c < NCAND; c++) {
        int j = cand[wid][c];
        const float* xj = g_nrm + ((size_t)b*SS + j)*DD;
        float s = 0.f;
        #pragma unroll
        for (int q = 0; q < DD/32; q++) s += xi[lane + q*32] * xj[lane + q*32];
        #pragma unroll
        for (int o = 16; o > 0; o >>= 1) s += __shfl_xor_sync(0xffffffffu, s, o);
        if (lane == 0) ex[wid][c] = s;
    }
    __syncwarp();

    if (lane == 0) {
        int iloc = row - b*SS;
        bool used[NCAND] = {};
        for (int p = 0; p < 3; p++) {
            float bv = NEG_INF; int bc = -1;
            for (int c = 0; c < NCAND; c++) {
                if (used[c]) continue;
                if (bc < 0 || ex[wid][c] > bv) { bv = ex[wid][c]; bc = c; }
            }
            used[bc] = true;
            int j = cand[wid][bc];
            float w = ex[wid][bc];
            // forward edge (row -> j)
            int pos = atomicAdd(&g_acnt[row], 1);
            if (pos < ACAP) { g_aidx[(size_t)row*ACAP + pos] = j; g_awt[(size_t)row*ACAP + pos] = w; }
            // reverse edge (j -> row)
            int rj = b*SS + j;
            int pos2 = atomicAdd(&g_acnt[rj], 1);
            if (pos2 < ACAP) { g_aidx[(size_t)rj*ACAP + pos2] = iloc; g_awt[(size_t)rj*ACAP + pos2] = w; }
        }
    }
}

// ---------------- 5. neighbor aggregation from weighted lists -> combined[256:512] hi/lo ----------------
__global__ void k_agg(const float* __restrict__ x) {
    int row = blockIdx.x;
    int b = row / SS;
    __shared__ int   sj[ACAP];
    __shared__ float sw[ACAP];
    __shared__ int   m;
    int t = threadIdx.x;

    int n = min(g_acnt[row], ACAP);
    if (t < n) {
        sj[t] = g_aidx[(size_t)row*ACAP + t];
        sw[t] = g_awt[(size_t)row*ACAP + t];
    }
    __syncthreads();

    if (t == 0) {
        // insertion sort by index (deterministic order), then dedup
        for (int a = 1; a < n; a++) {
            int j = sj[a]; float w = sw[a];
            int p = a - 1;
            while (p >= 0 && sj[p] > j) { sj[p+1] = sj[p]; sw[p+1] = sw[p]; p--; }
            sj[p+1] = j; sw[p+1] = w;
        }
        int mm = 0;
        for (int a = 0; a < n; a++) {
            if (a == 0 || sj[a] != sj[a-1]) { sj[mm] = sj[a]; sw[mm] = sw[a]; mm++; }
        }
        m = mm;
    }
    __syncthreads();
    int mm = m;

    float csum = 0.f;
    for (int l = 0; l < mm; l++) csum += sw[l];
    float acc = 0.f;
    for (int l = 0; l < mm; l++)
        acc += sw[l] * x[((size_t)b*SS + sj[l])*DD + t];
    float mval = acc / fmaxf(csum, 1.0f);
    __nv_bfloat16 h = __float2bfloat16(mval);
    g_chi[(size_t)row*KF + DD + t] = h;
    g_clo[(size_t)row*KF + DD + t] = __float2bfloat16(mval - __bfloat162float(h));
}

// ---------------- 6. projection GEMM via bf16 HMMA 3-split + bias + residual ----------------
__global__ void __launch_bounds__(256, 2) k_out2(const float* __restrict__ x,
                                                 const float* __restrict__ bias) {
    extern __shared__ char smem[];
    uint32_t sb = smem_u32(smem);
    int tid = threadIdx.x;
    int lane = tid & 31, wid = tid >> 5;
    int wm = wid & 3, wn = wid >> 2;        // 4 x 2 warps, warp tile 32x32

    int bx = blockIdx.x;
    int rA = (bx >> 2) * 128, cB = (bx & 3) * 64;

    const uint32_t AH = sb, AL = sb + OUT_A_B, BH = sb + 2*OUT_A_B, BL = sb + 2*OUT_A_B + OUT_B_B;

    float acc[2][4][4];
    #pragma unroll
    for (int i = 0; i < 2; i++)
        #pragma unroll
        for (int j = 0; j < 4; j++)
            #pragma unroll
            for (int q = 0; q < 4; q++) acc[i][j][q] = 0.f;

    int ar = lane & 15, aseg = lane >> 4;
    int br = lane & 7, bsel = lane >> 3;
    int bnoff = (bsel >> 1) * 8, bkoff = (bsel & 1) * 8;

    int lrow = tid >> 1, lcol = (tid & 1) * 32;

    for (int c = 0; c < KF/KC; c++) {       // 8 chunks of 64
        int kk = c * KC;
        {
            const uint4* pAh = (const uint4*)(g_chi + (size_t)(rA+lrow)*KF + kk + lcol);
            const uint4* pAl = (const uint4*)(g_clo + (size_t)(rA+lrow)*KF + kk + lcol);
            uint32_t so = (uint32_t)(lrow*LDA + lcol) * 2;
            #pragma unroll
            for (int q = 0; q < 4; q++) {
                *(uint4*)(smem + (AH - sb) + so + q*16) = pAh[q];
                *(uint4*)(smem + (AL - sb) + so + q*16) = pAl[q];
            }
            if (tid < 128) {
                const uint4* pBh = (const uint4*)(g_whi + (size_t)(cB+lrow)*KF + kk + lcol);
                const uint4* pBl = (const uint4*)(g_wlo + (size_t)(cB+lrow)*KF + kk + lcol);
                #pragma unroll
                for (int q = 0; q < 4; q++) {
                    *(uint4*)(smem + (BH - sb) + so + q*16) = pBh[q];
                    *(uint4*)(smem + (BL - sb) + so + q*16) = pBl[q];
                }
            }
        }
        __syncthreads();

        #pragma unroll
        for (int ks = 0; ks < KC/16; ks++) {
            int kb = ks * 16;
            uint32_t ah[2][4], al[2][4];
            #pragma unroll
            for (int mt = 0; mt < 2; mt++) {
                uint32_t ao = (uint32_t)((wm*32 + mt*16 + ar)*LDA + kb + aseg*8) * 2;
                ldmx4(ah[mt], AH + ao);
                ldmx4(al[mt], AL + ao);
            }
            #pragma unroll
            for (int np = 0; np < 2; np++) {
                uint32_t bo = (uint32_t)((wn*32 + np*16 + bnoff + br)*LDA + kb + bkoff) * 2;
                uint32_t bh[4], bl[4];
                ldmx4(bh, BH + bo);
                ldmx4(bl, BL + bo);
                #pragma unroll
                for (int mt = 0; mt < 2; mt++) {
                    #pragma unroll
                    for (int sub = 0; sub < 2; sub++) {
                        int nt = np*2 + sub;
                        mma16816(acc[mt][nt], ah[mt], bh[sub*2], bh[sub*2+1]);
                        mma16816(acc[mt][nt], ah[mt], bl[sub*2], bl[sub*2+1]);
                        mma16816(acc[mt][nt], al[mt], bh[sub*2], bh[sub*2+1]);
                    }
                }
            }
        }
        __syncthreads();
    }

    int fr = lane >> 2, fc = (lane & 3) * 2;
    #pragma unroll
    for (int mt = 0; mt < 2; mt++) {
        #pragma unroll
        for (int nt = 0; nt < 4; nt++) {
            int r0 = rA + wm*32 + mt*16 + fr;
            int cc = cB + wn*32 + nt*8 + fc;
            g_y[(size_t)r0*DD + cc]       = x[(size_t)r0*DD + cc]       + acc[mt][nt][0] + bias[cc];
            g_y[(size_t)r0*DD + cc+1]     = x[(size_t)r0*DD + cc+1]     + acc[mt][nt][1] + bias[cc+1];
            g_y[(size_t)(r0+8)*DD + cc]   = x[(size_t)(r0+8)*DD + cc]   + acc[mt][nt][2] + bias[cc];
            g_y[(size_t)(r0+8)*DD + cc+1] = x[(size_t)(r0+8)*DD + cc+1] + acc[mt][nt][3] + bias[cc+1];
        }
    }
}

// ---------------- 7. LayerNorm ----------------
__global__ void k_ln(const float* __restrict__ gamma, const float* __restrict__ beta,
                     float* __restrict__ out) {
    int row = blockIdx.x;
    int t = threadIdx.x;
    float v = g_y[(size_t)row*DD + t];
    __shared__ float sh[8];

    float s = v;
    #pragma unroll
    for (int o = 16; o > 0; o >>= 1) s += __shfl_xor_sync(0xffffffffu, s, o);
    if ((t & 31) == 0) sh[t >> 5] = s;
    __syncthreads();
    if (t < 32) {
        float z = (t < 8) ? sh[t] : 0.f;
        #pragma unroll
        for (int o = 4; o > 0; o >>= 1) z += __shfl_xor_sync(0xffffffffu, z, o);
        if (t == 0) sh[0] = z;
    }
    __syncthreads();
    float mu = sh[0] * (1.0f/DD);
    __syncthreads();

    float d = v - mu;
    float s2 = d*d;
    #pragma unroll
    for (int o = 16; o > 0; o >>= 1) s2 += __shfl_xor_sync(0xffffffffu, s2, o);
    if ((t & 31) == 0) sh[t >> 5] = s2;
    __syncthreads();
    if (t < 32) {
        float z = (t < 8) ? sh[t] : 0.f;
        #pragma unroll
        for (int o = 4; o > 0; o >>= 1) z += __shfl_xor_sync(0xffffffffu, z, o);
        if (t == 0) sh[0] = z;
    }
    __syncthreads();
    float var = sh[0] * (1.0f/DD);

    out[(size_t)row*DD + t] = d * rsqrtf(var + 1e-5f) * gamma[t] + beta[t];
}

// ---------------- launch ----------------
extern "C" void kernel_launch(void* const* d_in, const int* in_sizes, int n_in,
                              void* d_out, int out_size) {
    const float* x     = (const float*)d_in[0];
    const float* W     = (const float*)d_in[1];
    const float* bias  = (const float*)d_in[2];
    const float* gamma = (const float*)d_in[3];
    const float* beta  = (const float*)d_in[4];
    float* out = (float*)d_out;

    cudaFuncSetAttribute(k_sim3, cudaFuncAttributeMaxDynamicSharedMemorySize, SIM_SMEM);
    cudaFuncSetAttribute(k_out2, cudaFuncAttributeMaxDynamicSharedMemorySize, OUT_SMEM);

    k_clr<<<(RR + 255)/256, 256>>>();
    k_norm<<<RR, 256>>>(x);
    k_wsplit<<<(DD*KF)/256, 256>>>(W);
    k_sim3<<<dim3(TRI2, BB), 256, SIM_SMEM>>>();
    k_mrg<<<RR/8, 256>>>();
    k_agg<<<RR, 256>>>(x);
    k_out2<<<(RR/128)*4, 256, OUT_SMEM>>>(x, bias);
    k_ln<<<RR, 256>>>(gamma, beta, out);
}

// round 14
// speedup vs baseline: 1.0438x; 1.0438x over previous
#include <cuda_runtime.h>
#include <cuda_bf16.h>
#include <cuda_fp16.h>
#include <math.h>
#include <stdint.h>

#define BB 8
#define SS 2048
#define DD 256
#define RR (BB*SS)          // 16384 rows total
#define NEG_INF -1.0e30f

// ----- HMMA sim tiling -----
#define TS2 128
#define NT2 (SS/TS2)                 // 16
#define TRI2 (NT2*(NT2+1)/2)         // 136
#define KC 64
#define NCHUNK (DD/KC)               // 4
#define LDA 72                       // padded smem row stride (2B elems)
#define TILE_B (128*LDA*2)           // 18432 bytes per operand tile
#define SIM_STAGE_B (2*TILE_B)       // A+B per stage = 36864
#define SIM_SMEM (2*SIM_STAGE_B)     // 73728 (covers key buffer 128*132*4=67584)

#define NCAND 10                     // merge width (rescored exactly)
#define ACAP 96                      // adjacency list capacity per row

// ----- HMMA out tiling -----
#define KF (2*DD)                    // 512
#define OUT_A_B (128*LDA*2)          // 18432
#define OUT_B_B (64*LDA*2)           // 9216
#define OUT_SMEM (2*OUT_A_B + 2*OUT_B_B)   // 55296

// ---------------- static scratch ----------------
__device__ float    g_nrm[(size_t)RR*DD];            // 16 MB exact normalized rows
__device__ __half   g_f16[(size_t)RR*DD];            // 8 MB fp16 normalized rows
__device__ uint32_t g_cand[(size_t)RR*256];          // 16.8 MB packed candidate keys
__device__ int      g_acnt[RR];                      // adjacency counts
__device__ int      g_aidx[(size_t)RR*ACAP];         // adjacency indices (batch-local)
__device__ float    g_awt[(size_t)RR*ACAP];          // adjacency weights (exact fp32)
__device__ __nv_bfloat16 g_chi[(size_t)RR*KF];       // 16 MB combined hi
__device__ __nv_bfloat16 g_clo[(size_t)RR*KF];       // 16 MB combined lo
__device__ __nv_bfloat16 g_whi[(size_t)DD*KF];       // 256 KB
__device__ __nv_bfloat16 g_wlo[(size_t)DD*KF];       // 256 KB
__device__ float    g_y[(size_t)RR*DD];              // 16 MB

__device__ __forceinline__ uint32_t smem_u32(const void* p) {
    uint32_t a;
    asm("{ .reg .u64 t; cvta.to.shared.u64 t, %1; cvt.u32.u64 %0, t; }" : "=r"(a) : "l"(p));
    return a;
}
__device__ __forceinline__ void ldmx4(uint32_t* r, uint32_t addr) {
    asm volatile("ldmatrix.sync.aligned.m8n8.x4.shared.b16 {%0,%1,%2,%3}, [%4];"
        : "=r"(r[0]), "=r"(r[1]), "=r"(r[2]), "=r"(r[3]) : "r"(addr));
}
__device__ __forceinline__ void mma16816(float* c, const uint32_t* a, uint32_t b0, uint32_t b1) {
    asm volatile("mma.sync.aligned.m16n8k16.row.col.f32.bf16.bf16.f32 "
        "{%0,%1,%2,%3}, {%4,%5,%6,%7}, {%8,%9}, {%0,%1,%2,%3};"
        : "+f"(c[0]), "+f"(c[1]), "+f"(c[2]), "+f"(c[3])
        : "r"(a[0]), "r"(a[1]), "r"(a[2]), "r"(a[3]), "r"(b0), "r"(b1));
}
__device__ __forceinline__ void mma16816h(float* c, const uint32_t* a, uint32_t b0, uint32_t b1) {
    asm volatile("mma.sync.aligned.m16n8k16.row.col.f32.f16.f16.f32 "
        "{%0,%1,%2,%3}, {%4,%5,%6,%7}, {%8,%9}, {%0,%1,%2,%3};"
        : "+f"(c[0]), "+f"(c[1]), "+f"(c[2]), "+f"(c[3])
        : "r"(a[0]), "r"(a[1]), "r"(a[2]), "r"(a[3]), "r"(b0), "r"(b1));
}
__device__ __forceinline__ void cpa16(uint32_t dst, const void* src) {
    asm volatile("cp.async.ca.shared.global [%0], [%1], 16;" :: "r"(dst), "l"(src));
}
#define CP_COMMIT() asm volatile("cp.async.commit_group;" ::: "memory")
#define CP_WAIT(n)  asm volatile("cp.async.wait_group %0;" :: "n"(n) : "memory")

// cheap monotone pack: clamp negatives to 0 (positive float bits are order-preserving),
// keep top 21 value bits, pack 11-bit index low.
__device__ __forceinline__ uint32_t f2key(float f, int j) {
    uint32_t u = __float_as_uint(fmaxf(f, 0.0f));
    return (u & 0xFFFFF800u) | (uint32_t)j;
}
// sorted-descending top-8 insert (guarded)
__device__ __forceinline__ void ins8(uint32_t* tk, uint32_t k) {
    if (k > tk[7]) {
        #pragma unroll
        for (int p = 7; p >= 1; p--)
            tk[p] = (k > tk[p-1]) ? tk[p-1] : (k > tk[p] ? k : tk[p]);
        if (k > tk[0]) tk[0] = k;
    }
}
// group-guarded scan of 4 packed keys
__device__ __forceinline__ void ins8x4(uint32_t* tk, uint32_t k0, uint32_t k1, uint32_t k2, uint32_t k3) {
    uint32_t m0 = k0 > k1 ? k0 : k1;
    uint32_t m1 = k2 > k3 ? k2 : k3;
    if ((m0 > m1 ? m0 : m1) > tk[7]) {
        ins8(tk, k0); ins8(tk, k1); ins8(tk, k2); ins8(tk, k3);
    }
}

// ---------------- 0. clear adjacency counters ----------------
__global__ void k_clr() {
    int t = blockIdx.x*256 + threadIdx.x;
    if (t < RR) g_acnt[t] = 0;
}

// ---------------- 1. row L2-normalize -> fp32 + fp16; raw x -> combined[0:256] ----------------
__global__ void k_norm(const float* __restrict__ x) {
    int row = blockIdx.x;
    int t = threadIdx.x;
    float v = x[(size_t)row*DD + t];
    __shared__ float sh[8];
    float s = v*v;
    #pragma unroll
    for (int o = 16; o > 0; o >>= 1) s += __shfl_xor_sync(0xffffffffu, s, o);
    if ((t & 31) == 0) sh[t >> 5] = s;
    __syncthreads();
    if (t < 32) {
        float z = (t < 8) ? sh[t] : 0.f;
        #pragma unroll
        for (int o = 4; o > 0; o >>= 1) z += __shfl_xor_sync(0xffffffffu, z, o);
        if (t == 0) sh[0] = z;
    }
    __syncthreads();
    float nrm = sqrtf(sh[0]);
    float sc = 1.f / fmaxf(nrm, 1e-12f);
    float nv = v * sc;
    g_nrm[(size_t)row*DD + t] = nv;
    g_f16[(size_t)row*DD + t] = __float2half(nv);
    __nv_bfloat16 xh = __float2bfloat16(v);
    g_chi[(size_t)row*KF + t] = xh;
    g_clo[(size_t)row*KF + t] = __float2bfloat16(v - __bfloat162float(xh));
}

// ---------------- 1b. W hi/lo split ----------------
__global__ void k_wsplit(const float* __restrict__ W) {
    int t = blockIdx.x*256 + threadIdx.x;   // DD*KF = 131072
    float v = W[t];
    __nv_bfloat16 h = __float2bfloat16(v);
    g_whi[t] = h;
    g_wlo[t] = __float2bfloat16(v - __bfloat162float(h));
}

// ---------------- 2. sim tiles via single fp16 HMMA, cp.async 2-stage; fused top-8 candidates ----------------
__global__ void __launch_bounds__(256, 2) k_sim3() {
    extern __shared__ char smem[];
    uint32_t sb = smem_u32(smem);
    int tid = threadIdx.x;
    int lane = tid & 31, wid = tid >> 5;
    int wm = wid & 3, wn = wid >> 2;

    int t = blockIdx.x;
    int bi = 0;
    while ((bi+1)*(bi+2)/2 <= t) bi++;
    int bj = t - bi*(bi+1)/2;           // bi >= bj
    int b = blockIdx.y;
    int rA = bi*TS2, rB = bj*TS2;

    const __half* hb = g_f16 + (size_t)b*SS*DD;

    float acc[2][8][4];
    #pragma unroll
    for (int i = 0; i < 2; i++)
        #pragma unroll
        for (int j = 0; j < 8; j++)
            #pragma unroll
            for (int q = 0; q < 4; q++) acc[i][j][q] = 0.f;

    int ar = lane & 15, aseg = lane >> 4;
    int br = lane & 7, bsel = lane >> 3;
    int bnoff = (bsel >> 1) * 8, bkoff = (bsel & 1) * 8;

    int lrow = tid >> 1, lcol = (tid & 1) * 32;
    uint32_t so = (uint32_t)(lrow*LDA + lcol) * 2;

    // prologue: chunk 0 -> stage 0
    {
        const char* gA = (const char*)(hb + (size_t)(rA+lrow)*DD + lcol);
        const char* gB = (const char*)(hb + (size_t)(rB+lrow)*DD + lcol);
        uint32_t dA = sb + so, dB = sb + TILE_B + so;
        #pragma unroll
        for (int q = 0; q < 4; q++) { cpa16(dA + q*16, gA + q*16); cpa16(dB + q*16, gB + q*16); }
        CP_COMMIT();
    }

    for (int c = 0; c < NCHUNK; c++) {
        if (c + 1 < NCHUNK) {
            int kk = (c+1) * KC;
            int s = (c+1) & 1;
            const char* gA = (const char*)(hb + (size_t)(rA+lrow)*DD + kk + lcol);
            const char* gB = (const char*)(hb + (size_t)(rB+lrow)*DD + kk + lcol);
            uint32_t dA = sb + s*SIM_STAGE_B + so, dB = dA + TILE_B;
            #pragma unroll
            for (int q = 0; q < 4; q++) { cpa16(dA + q*16, gA + q*16); cpa16(dB + q*16, gB + q*16); }
            CP_COMMIT();
            CP_WAIT(1);
        } else {
            CP_WAIT(0);
        }
        __syncthreads();

        uint32_t stA = sb + (c & 1)*SIM_STAGE_B;
        uint32_t stB = stA + TILE_B;
        #pragma unroll
        for (int ks = 0; ks < KC/16; ks++) {
            int kb = ks * 16;
            uint32_t ah[2][4];
            #pragma unroll
            for (int mt = 0; mt < 2; mt++) {
                uint32_t ao = (uint32_t)((wm*32 + mt*16 + ar)*LDA + kb + aseg*8) * 2;
                ldmx4(ah[mt], stA + ao);
            }
            #pragma unroll
            for (int np = 0; np < 4; np++) {
                uint32_t bo = (uint32_t)((wn*64 + np*16 + bnoff + br)*LDA + kb + bkoff) * 2;
                uint32_t bh[4];
                ldmx4(bh, stB + bo);
                #pragma unroll
                for (int mt = 0; mt < 2; mt++)
                    #pragma unroll
                    for (int sub = 0; sub < 2; sub++)
                        mma16816h(acc[mt][np*2 + sub], ah[mt], bh[sub*2], bh[sub*2+1]);
            }
        }
        __syncthreads();
    }

    // -------- epilogue: single key write, row scan + in-place column scan --------
    uint32_t* Ck = (uint32_t*)smem;     // [128][132], key = (val21 | col11)
    int fr = lane >> 2, fc = (lane & 3) * 2;

    #pragma unroll
    for (int mt = 0; mt < 2; mt++) {
        #pragma unroll
        for (int nt = 0; nt < 8; nt++) {
            int r0 = wm*32 + mt*16 + fr;
            int cc = wn*64 + nt*8 + fc;
            int g0 = rA + r0, g1 = rA + r0 + 8;
            int j0 = rB + cc, j1 = rB + cc + 1;
            Ck[r0*132 + cc]       = (g0 == j0) ? 0u : f2key(acc[mt][nt][0], j0);
            Ck[r0*132 + cc+1]     = (g0 == j1) ? 0u : f2key(acc[mt][nt][1], j1);
            Ck[(r0+8)*132 + cc]   = (g1 == j0) ? 0u : f2key(acc[mt][nt][2], j0);
            Ck[(r0+8)*132 + cc+1] = (g1 == j1) ? 0u : f2key(acc[mt][nt][3], j1);
        }
    }
    __syncthreads();

    // row scan: candidates for rows of tile bi (indices already packed = rB + col)
    {
        int row = tid >> 1, half = tid & 1;
        const uint32_t* src = Ck + row*132 + half*64;
        uint32_t tk[8];
        #pragma unroll
        for (int p = 0; p < 8; p++) tk[p] = 0u;
        #pragma unroll 4
        for (int c4 = 0; c4 < 16; c4++) {
            uint4 kk = *(const uint4*)(src + c4*4);
            ins8x4(tk, kk.x, kk.y, kk.z, kk.w);
        }
        uint32_t* dst = g_cand + ((size_t)(b*SS + rA + row))*256 + (bj*2 + half)*8;
        *(uint4*)(dst)     = make_uint4(tk[0], tk[1], tk[2], tk[3]);
        *(uint4*)(dst + 4) = make_uint4(tk[4], tk[5], tk[6], tk[7]);
    }

    // column scan (no rewrite): candidates for rows of tile bj; re-pack index = rA + r
    if (bi != bj) {
        int col = tid >> 1, half = tid & 1;
        int rbase = half*64;
        uint32_t tk[8];
        #pragma unroll
        for (int p = 0; p < 8; p++) tk[p] = 0u;
        const uint32_t* src = Ck + (size_t)rbase*132 + col;
        #pragma unroll 4
        for (int r4 = 0; r4 < 16; r4++) {
            uint32_t k0 = src[(r4*4+0)*132];
            uint32_t k1 = src[(r4*4+1)*132];
            uint32_t k2 = src[(r4*4+2)*132];
            uint32_t k3 = src[(r4*4+3)*132];
            int rg = rA + rbase + r4*4;
            k0 = (k0 & 0xFFFFF800u) | (uint32_t)(rg+0);
            k1 = (k1 & 0xFFFFF800u) | (uint32_t)(rg+1);
            k2 = (k2 & 0xFFFFF800u) | (uint32_t)(rg+2);
            k3 = (k3 & 0xFFFFF800u) | (uint32_t)(rg+3);
            ins8x4(tk, k0, k1, k2, k3);
        }
        uint32_t* dst = g_cand + ((size_t)(b*SS + rB + col))*256 + (bi*2 + half)*8;
        *(uint4*)(dst)     = make_uint4(tk[0], tk[1], tk[2], tk[3]);
        *(uint4*)(dst + 4) = make_uint4(tk[4], tk[5], tk[6], tk[7]);
    }
}

// ---------------- 3. merge keys -> top-10 -> exact rescore -> top-3 -> scatter weighted edges ----------------
// grid RR/8, 256 threads, warp per row
__global__ void __launch_bounds__(256) k_mrg() {
    __shared__ int   cand[8][NCAND];
    __shared__ float ex[8][NCAND];
    int tid = threadIdx.x;
    int lane = tid & 31, wid = tid >> 5;
    int row = blockIdx.x*8 + wid;
    int b = row / SS;
    int iloc = row - b*SS;

    const uint32_t* src = g_cand + (size_t)row*256;
    uint32_t k[8];
    #pragma unroll
    for (int p = 0; p < 8; p++) k[p] = src[p*32 + lane];   // coalesced

    for (int p = 0; p < NCAND; p++) {
        uint32_t bk = 0u;
        #pragma unroll
        for (int q = 0; q < 8; q++) bk = (k[q] > bk) ? k[q] : bk;
        #pragma unroll
        for (int o = 16; o > 0; o >>= 1) {
            uint32_t ov = __shfl_xor_sync(0xffffffffu, bk, o);
            bk = (ov > bk) ? ov : bk;
        }
        #pragma unroll
        for (int q = 0; q < 8; q++) if (k[q] == bk) k[q] = 0u;
        if (lane == 0) cand[wid][p] = (int)(bk & 0x7FFu);
    }
    __syncwarp();

    // exact fp32 rescore (self-candidates rejected)
    const float* xi = g_nrm + (size_t)row*DD;
    for (int c = 0; c < NCAND; c++) {
        int j = cand[wid][c];
        const float* xj = g_nrm + ((size_t)b*SS + j)*DD;
        float s = 0.f;
        #pragma unroll
        for (int q = 0; q < DD/32; q++) s += xi[lane + q*32] * xj[lane + q*32];
        #pragma unroll
        for (int o = 16; o > 0; o >>= 1) s += __shfl_xor_sync(0xffffffffu, s, o);
        if (lane == 0) ex[wid][c] = (j == iloc) ? NEG_INF : s;
    }
    __syncwarp();

    if (lane == 0) {
        bool used[NCAND] = {};
        for (int p = 0; p < 3; p++) {
            float bv = NEG_INF; int bc = -1;
            for (int c = 0; c < NCAND; c++) {
                if (used[c]) continue;
                if (bc < 0 || ex[wid][c] > bv) { bv = ex[wid][c]; bc = c; }
            }
            used[bc] = true;
            int j = cand[wid][bc];
            float w = ex[wid][bc];
            int pos = atomicAdd(&g_acnt[row], 1);
            if (pos < ACAP) { g_aidx[(size_t)row*ACAP + pos] = j; g_awt[(size_t)row*ACAP + pos] = w; }
            int rj = b*SS + j;
            int pos2 = atomicAdd(&g_acnt[rj], 1);
            if (pos2 < ACAP) { g_aidx[(size_t)rj*ACAP + pos2] = iloc; g_awt[(size_t)rj*ACAP + pos2] = w; }
        }
    }
}

// ---------------- 5. neighbor aggregation from weighted lists -> combined[256:512] hi/lo ----------------
__global__ void k_agg(const float* __restrict__ x) {
    int row = blockIdx.x;
    int b = row / SS;
    __shared__ int   sj[ACAP];
    __shared__ float sw[ACAP];
    __shared__ int   m;
    int t = threadIdx.x;

    int n = min(g_acnt[row], ACAP);
    if (t < n) {
        sj[t] = g_aidx[(size_t)row*ACAP + t];
        sw[t] = g_awt[(size_t)row*ACAP + t];
    }
    __syncthreads();

    if (t == 0) {
        for (int a = 1; a < n; a++) {
            int j = sj[a]; float w = sw[a];
            int p = a - 1;
            while (p >= 0 && sj[p] > j) { sj[p+1] = sj[p]; sw[p+1] = sw[p]; p--; }
            sj[p+1] = j; sw[p+1] = w;
        }
        int mm = 0;
        for (int a = 0; a < n; a++) {
            if (a == 0 || sj[a] != sj[a-1]) { sj[mm] = sj[a]; sw[mm] = sw[a]; mm++; }
        }
        m = mm;
    }
    __syncthreads();
    int mm = m;

    float csum = 0.f;
    for (int l = 0; l < mm; l++) csum += sw[l];
    float acc = 0.f;
    for (int l = 0; l < mm; l++)
        acc += sw[l] * x[((size_t)b*SS + sj[l])*DD + t];
    float mval = acc / fmaxf(csum, 1.0f);
    __nv_bfloat16 h = __float2bfloat16(mval);
    g_chi[(size_t)row*KF + DD + t] = h;
    g_clo[(size_t)row*KF + DD + t] = __float2bfloat16(mval - __bfloat162float(h));
}

// ---------------- 6. projection GEMM via bf16 HMMA 3-split + bias + residual ----------------
__global__ void __launch_bounds__(256, 2) k_out2(const float* __restrict__ x,
                                                 const float* __restrict__ bias) {
    extern __shared__ char smem[];
    uint32_t sb = smem_u32(smem);
    int tid = threadIdx.x;
    int lane = tid & 31, wid = tid >> 5;
    int wm = wid & 3, wn = wid >> 2;        // 4 x 2 warps, warp tile 32x32

    int bx = blockIdx.x;
    int rA = (bx >> 2) * 128, cB = (bx & 3) * 64;

    const uint32_t AH = sb, AL = sb + OUT_A_B, BH = sb + 2*OUT_A_B, BL = sb + 2*OUT_A_B + OUT_B_B;

    float acc[2][4][4];
    #pragma unroll
    for (int i = 0; i < 2; i++)
        #pragma unroll
        for (int j = 0; j < 4; j++)
            #pragma unroll
            for (int q = 0; q < 4; q++) acc[i][j][q] = 0.f;

    int ar = lane & 15, aseg = lane >> 4;
    int br = lane & 7, bsel = lane >> 3;
    int bnoff = (bsel >> 1) * 8, bkoff = (bsel & 1) * 8;

    int lrow = tid >> 1, lcol = (tid & 1) * 32;

    for (int c = 0; c < KF/KC; c++) {       // 8 chunks of 64
        int kk = c * KC;
        {
            const uint4* pAh = (const uint4*)(g_chi + (size_t)(rA+lrow)*KF + kk + lcol);
            const uint4* pAl = (const uint4*)(g_clo + (size_t)(rA+lrow)*KF + kk + lcol);
            uint32_t so = (uint32_t)(lrow*LDA + lcol) * 2;
            #pragma unroll
            for (int q = 0; q < 4; q++) {
                *(uint4*)(smem + (AH - sb) + so + q*16) = pAh[q];
                *(uint4*)(smem + (AL - sb) + so + q*16) = pAl[q];
            }
            if (tid < 128) {
                const uint4* pBh = (const uint4*)(g_whi + (size_t)(cB+lrow)*KF + kk + lcol);
                const uint4* pBl = (const uint4*)(g_wlo + (size_t)(cB+lrow)*KF + kk + lcol);
                #pragma unroll
                for (int q = 0; q < 4; q++) {
                    *(uint4*)(smem + (BH - sb) + so + q*16) = pBh[q];
                    *(uint4*)(smem + (BL - sb) + so + q*16) = pBl[q];
                }
            }
        }
        __syncthreads();

        #pragma unroll
        for (int ks = 0; ks < KC/16; ks++) {
            int kb = ks * 16;
            uint32_t ah[2][4], al[2][4];
            #pragma unroll
            for (int mt = 0; mt < 2; mt++) {
                uint32_t ao = (uint32_t)((wm*32 + mt*16 + ar)*LDA + kb + aseg*8) * 2;
                ldmx4(ah[mt], AH + ao);
                ldmx4(al[mt], AL + ao);
            }
            #pragma unroll
            for (int np = 0; np < 2; np++) {
                uint32_t bo = (uint32_t)((wn*32 + np*16 + bnoff + br)*LDA + kb + bkoff) * 2;
                uint32_t bh[4], bl[4];
                ldmx4(bh, BH + bo);
                ldmx4(bl, BL + bo);
                #pragma unroll
                for (int mt = 0; mt < 2; mt++) {
                    #pragma unroll
                    for (int sub = 0; sub < 2; sub++) {
                        int nt = np*2 + sub;
                        mma16816(acc[mt][nt], ah[mt], bh[sub*2], bh[sub*2+1]);
                        mma16816(acc[mt][nt], ah[mt], bl[sub*2], bl[sub*2+1]);
                        mma16816(acc[mt][nt], al[mt], bh[sub*2], bh[sub*2+1]);
                    }
                }
            }
        }
        __syncthreads();
    }

    int fr = lane >> 2, fc = (lane & 3) * 2;
    #pragma unroll
    for (int mt = 0; mt < 2; mt++) {
        #pragma unroll
        for (int nt = 0; nt < 4; nt++) {
            int r0 = rA + wm*32 + mt*16 + fr;
            int cc = cB + wn*32 + nt*8 + fc;
            g_y[(size_t)r0*DD + cc]       = x[(size_t)r0*DD + cc]       + acc[mt][nt][0] + bias[cc];
            g_y[(size_t)r0*DD + cc+1]     = x[(size_t)r0*DD + cc+1]     + acc[mt][nt][1] + bias[cc+1];
            g_y[(size_t)(r0+8)*DD + cc]   = x[(size_t)(r0+8)*DD + cc]   + acc[mt][nt][2] + bias[cc];
            g_y[(size_t)(r0+8)*DD + cc+1] = x[(size_t)(r0+8)*DD + cc+1] + acc[mt][nt][3] + bias[cc+1];
        }
    }
}

// ---------------- 7. LayerNorm ----------------
__global__ void k_ln(const float* __restrict__ gamma, const float* __restrict__ beta,
                     float* __restrict__ out) {
    int row = blockIdx.x;
    int t = threadIdx.x;
    float v = g_y[(size_t)row*DD + t];
    __shared__ float sh[8];

    float s = v;
    #pragma unroll
    for (int o = 16; o > 0; o >>= 1) s += __shfl_xor_sync(0xffffffffu, s, o);
    if ((t & 31) == 0) sh[t >> 5] = s;
    __syncthreads();
    if (t < 32) {
        float z = (t < 8) ? sh[t] : 0.f;
        #pragma unroll
        for (int o = 4; o > 0; o >>= 1) z += __shfl_xor_sync(0xffffffffu, z, o);
        if (t == 0) sh[0] = z;
    }
    __syncthreads();
    float mu = sh[0] * (1.0f/DD);
    __syncthreads();

    float d = v - mu;
    float s2 = d*d;
    #pragma unroll
    for (int o = 16; o > 0; o >>= 1) s2 += __shfl_xor_sync(0xffffffffu, s2, o);
    if ((t & 31) == 0) sh[t >> 5] = s2;
    __syncthreads();
    if (t < 32) {
        float z = (t < 8) ? sh[t] : 0.f;
        #pragma unroll
        for (int o = 4; o > 0; o >>= 1) z += __shfl_xor_sync(0xffffffffu, z, o);
        if (t == 0) sh[0] = z;
    }
    __syncthreads();
    float var = sh[0] * (1.0f/DD);

    out[(size_t)row*DD + t] = d * rsqrtf(var + 1e-5f) * gamma[t] + beta[t];
}

// ---------------- launch ----------------
extern "C" void kernel_launch(void* const* d_in, const int* in_sizes, int n_in,
                              void* d_out, int out_size) {
    const float* x     = (const float*)d_in[0];
    const float* W     = (const float*)d_in[1];
    const float* bias  = (const float*)d_in[2];
    const float* gamma = (const float*)d_in[3];
    const float* beta  = (const float*)d_in[4];
    float* out = (float*)d_out;

    cudaFuncSetAttribute(k_sim3, cudaFuncAttributeMaxDynamicSharedMemorySize, SIM_SMEM);
    cudaFuncSetAttribute(k_out2, cudaFuncAttributeMaxDynamicSharedMemorySize, OUT_SMEM);

    k_clr<<<(RR + 255)/256, 256>>>();
    k_norm<<<RR, 256>>>(x);
    k_wsplit<<<(DD*KF)/256, 256>>>(W);
    k_sim3<<<dim3(TRI2, BB), 256, SIM_SMEM>>>();
    k_mrg<<<RR/8, 256>>>();
    k_agg<<<RR, 256>>>(x);
    k_out2<<<(RR/128)*4, 256, OUT_SMEM>>>(x, bias);
    k_ln<<<RR, 256>>>(gamma, beta, out);
}

// round 15
// speedup vs baseline: 1.3824x; 1.3243x over previous
#include <cuda_runtime.h>
#include <cuda_fp16.h>
#include <math.h>
#include <stdint.h>

#define BB 8
#define SS 2048
#define DD 256
#define RR (BB*SS)          // 16384 rows total
#define NEG_INF -1.0e30f

// ----- HMMA sim tiling -----
#define TS2 128
#define NT2 (SS/TS2)                 // 16
#define TRI2 (NT2*(NT2+1)/2)         // 136
#define KC 64
#define NCHUNK (DD/KC)               // 4
#define LDA 72                       // padded smem row stride (2B elems)
#define TILE_B (128*LDA*2)           // 18432 bytes per operand tile
#define SIM_STAGE_B (2*TILE_B)       // A+B per stage = 36864
#define SIM_SMEM (2*SIM_STAGE_B)     // 73728 (covers key buffer 128*132*4=67584)

#define NCAND 10                     // merge width (rescored exactly)
#define ACAP 96                      // adjacency list capacity per row

// ----- HMMA out tiling -----
#define KF (2*DD)                    // 512
#define OUT_A_B (128*LDA*2)          // 18432
#define OUT_B_B (64*LDA*2)           // 9216
#define OUT_STAGE_B (OUT_A_B + OUT_B_B)    // 27648
#define OUT_SMEM (2*OUT_STAGE_B)           // 55296

// ---------------- static scratch ----------------
__device__ float    g_nrm[(size_t)RR*DD];            // 16 MB exact normalized rows
__device__ __half   g_f16[(size_t)RR*DD];            // 8 MB fp16 normalized rows
__device__ uint32_t g_cand[(size_t)RR*128];          // 8.4 MB packed candidate keys
__device__ int      g_acnt[RR];                      // adjacency counts
__device__ int      g_aidx[(size_t)RR*ACAP];         // adjacency indices (batch-local)
__device__ float    g_awt[(size_t)RR*ACAP];          // adjacency weights (exact fp32)
__device__ __half   g_cf16[(size_t)RR*KF];           // 16 MB combined fp16 [x | nm]
__device__ __half   g_wf16[(size_t)DD*KF];           // 256 KB W fp16
__device__ float    g_y[(size_t)RR*DD];              // 16 MB

__device__ __forceinline__ uint32_t smem_u32(const void* p) {
    uint32_t a;
    asm("{ .reg .u64 t; cvta.to.shared.u64 t, %1; cvt.u32.u64 %0, t; }" : "=r"(a) : "l"(p));
    return a;
}
__device__ __forceinline__ void ldmx4(uint32_t* r, uint32_t addr) {
    asm volatile("ldmatrix.sync.aligned.m8n8.x4.shared.b16 {%0,%1,%2,%3}, [%4];"
        : "=r"(r[0]), "=r"(r[1]), "=r"(r[2]), "=r"(r[3]) : "r"(addr));
}
__device__ __forceinline__ void mma16816h(float* c, const uint32_t* a, uint32_t b0, uint32_t b1) {
    asm volatile("mma.sync.aligned.m16n8k16.row.col.f32.f16.f16.f32 "
        "{%0,%1,%2,%3}, {%4,%5,%6,%7}, {%8,%9}, {%0,%1,%2,%3};"
        : "+f"(c[0]), "+f"(c[1]), "+f"(c[2]), "+f"(c[3])
        : "r"(a[0]), "r"(a[1]), "r"(a[2]), "r"(a[3]), "r"(b0), "r"(b1));
}
__device__ __forceinline__ void cpa16(uint32_t dst, const void* src) {
    asm volatile("cp.async.ca.shared.global [%0], [%1], 16;" :: "r"(dst), "l"(src));
}
#define CP_COMMIT() asm volatile("cp.async.commit_group;" ::: "memory")
#define CP_WAIT(n)  asm volatile("cp.async.wait_group %0;" :: "n"(n) : "memory")

// cheap monotone pack: clamp negatives to 0, keep top 21 value bits, 11-bit index low
__device__ __forceinline__ uint32_t f2key(float f, int j) {
    uint32_t u = __float_as_uint(fmaxf(f, 0.0f));
    return (u & 0xFFFFF800u) | (uint32_t)j;
}
// sorted-descending top-4 insert (guarded)
__device__ __forceinline__ void ins4(uint32_t* tk, uint32_t k) {
    if (k > tk[3]) {
        #pragma unroll
        for (int p = 3; p >= 1; p--)
            tk[p] = (k > tk[p-1]) ? tk[p-1] : (k > tk[p] ? k : tk[p]);
        if (k > tk[0]) tk[0] = k;
    }
}
__device__ __forceinline__ void ins4x4(uint32_t* tk, uint32_t k0, uint32_t k1, uint32_t k2, uint32_t k3) {
    uint32_t m0 = k0 > k1 ? k0 : k1;
    uint32_t m1 = k2 > k3 ? k2 : k3;
    if ((m0 > m1 ? m0 : m1) > tk[3]) {
        ins4(tk, k0); ins4(tk, k1); ins4(tk, k2); ins4(tk, k3);
    }
}

// ---------------- 0. clear adjacency counters ----------------
__global__ void k_clr() {
    int t = blockIdx.x*256 + threadIdx.x;
    if (t < RR) g_acnt[t] = 0;
}

// ---------------- 1. row L2-normalize -> fp32 + fp16; raw x -> combined[0:256] ----------------
__global__ void k_norm(const float* __restrict__ x) {
    int row = blockIdx.x;
    int t = threadIdx.x;
    float v = x[(size_t)row*DD + t];
    __shared__ float sh[8];
    float s = v*v;
    #pragma unroll
    for (int o = 16; o > 0; o >>= 1) s += __shfl_xor_sync(0xffffffffu, s, o);
    if ((t & 31) == 0) sh[t >> 5] = s;
    __syncthreads();
    if (t < 32) {
        float z = (t < 8) ? sh[t] : 0.f;
        #pragma unroll
        for (int o = 4; o > 0; o >>= 1) z += __shfl_xor_sync(0xffffffffu, z, o);
        if (t == 0) sh[0] = z;
    }
    __syncthreads();
    float nrm = sqrtf(sh[0]);
    float sc = 1.f / fmaxf(nrm, 1e-12f);
    float nv = v * sc;
    g_nrm[(size_t)row*DD + t] = nv;
    g_f16[(size_t)row*DD + t] = __float2half(nv);
    g_cf16[(size_t)row*KF + t] = __float2half(v);
}

// ---------------- 1b. W -> fp16 ----------------
__global__ void k_w16(const float* __restrict__ W) {
    int t = blockIdx.x*256 + threadIdx.x;   // DD*KF = 131072
    g_wf16[t] = __float2half(W[t]);
}

// ---------------- 2. sim tiles via single fp16 HMMA, cp.async 2-stage; fused top-4 candidates ----------------
__global__ void __launch_bounds__(256, 2) k_sim3() {
    extern __shared__ char smem[];
    uint32_t sb = smem_u32(smem);
    int tid = threadIdx.x;
    int lane = tid & 31, wid = tid >> 5;
    int wm = wid & 3, wn = wid >> 2;

    int t = blockIdx.x;
    int bi = 0;
    while ((bi+1)*(bi+2)/2 <= t) bi++;
    int bj = t - bi*(bi+1)/2;           // bi >= bj
    int b = blockIdx.y;
    int rA = bi*TS2, rB = bj*TS2;

    const __half* hb = g_f16 + (size_t)b*SS*DD;

    float acc[2][8][4];
    #pragma unroll
    for (int i = 0; i < 2; i++)
        #pragma unroll
        for (int j = 0; j < 8; j++)
            #pragma unroll
            for (int q = 0; q < 4; q++) acc[i][j][q] = 0.f;

    int ar = lane & 15, aseg = lane >> 4;
    int br = lane & 7, bsel = lane >> 3;
    int bnoff = (bsel >> 1) * 8, bkoff = (bsel & 1) * 8;

    int lrow = tid >> 1, lcol = (tid & 1) * 32;
    uint32_t so = (uint32_t)(lrow*LDA + lcol) * 2;

    // prologue: chunk 0 -> stage 0
    {
        const char* gA = (const char*)(hb + (size_t)(rA+lrow)*DD + lcol);
        const char* gB = (const char*)(hb + (size_t)(rB+lrow)*DD + lcol);
        uint32_t dA = sb + so, dB = sb + TILE_B + so;
        #pragma unroll
        for (int q = 0; q < 4; q++) { cpa16(dA + q*16, gA + q*16); cpa16(dB + q*16, gB + q*16); }
        CP_COMMIT();
    }

    for (int c = 0; c < NCHUNK; c++) {
        if (c + 1 < NCHUNK) {
            int kk = (c+1) * KC;
            int s = (c+1) & 1;
            const char* gA = (const char*)(hb + (size_t)(rA+lrow)*DD + kk + lcol);
            const char* gB = (const char*)(hb + (size_t)(rB+lrow)*DD + kk + lcol);
            uint32_t dA = sb + s*SIM_STAGE_B + so, dB = dA + TILE_B;
            #pragma unroll
            for (int q = 0; q < 4; q++) { cpa16(dA + q*16, gA + q*16); cpa16(dB + q*16, gB + q*16); }
            CP_COMMIT();
            CP_WAIT(1);
        } else {
            CP_WAIT(0);
        }
        __syncthreads();

        uint32_t stA = sb + (c & 1)*SIM_STAGE_B;
        uint32_t stB = stA + TILE_B;
        #pragma unroll
        for (int ks = 0; ks < KC/16; ks++) {
            int kb = ks * 16;
            uint32_t ah[2][4];
            #pragma unroll
            for (int mt = 0; mt < 2; mt++) {
                uint32_t ao = (uint32_t)((wm*32 + mt*16 + ar)*LDA + kb + aseg*8) * 2;
                ldmx4(ah[mt], stA + ao);
            }
            #pragma unroll
            for (int np = 0; np < 4; np++) {
                uint32_t bo = (uint32_t)((wn*64 + np*16 + bnoff + br)*LDA + kb + bkoff) * 2;
                uint32_t bh[4];
                ldmx4(bh, stB + bo);
                #pragma unroll
                for (int mt = 0; mt < 2; mt++)
                    #pragma unroll
                    for (int sub = 0; sub < 2; sub++)
                        mma16816h(acc[mt][np*2 + sub], ah[mt], bh[sub*2], bh[sub*2+1]);
            }
        }
        __syncthreads();
    }

    // -------- epilogue: single key write, row scan + in-place column scan, top-4 each --------
    uint32_t* Ck = (uint32_t*)smem;     // [128][132], key = (val21 | col11)
    int fr = lane >> 2, fc = (lane & 3) * 2;

    #pragma unroll
    for (int mt = 0; mt < 2; mt++) {
        #pragma unroll
        for (int nt = 0; nt < 8; nt++) {
            int r0 = wm*32 + mt*16 + fr;
            int cc = wn*64 + nt*8 + fc;
            int g0 = rA + r0, g1 = rA + r0 + 8;
            int j0 = rB + cc, j1 = rB + cc + 1;
            Ck[r0*132 + cc]       = (g0 == j0) ? 0u : f2key(acc[mt][nt][0], j0);
            Ck[r0*132 + cc+1]     = (g0 == j1) ? 0u : f2key(acc[mt][nt][1], j1);
            Ck[(r0+8)*132 + cc]   = (g1 == j0) ? 0u : f2key(acc[mt][nt][2], j0);
            Ck[(r0+8)*132 + cc+1] = (g1 == j1) ? 0u : f2key(acc[mt][nt][3], j1);
        }
    }
    __syncthreads();

    // row scan: candidates for rows of tile bi (indices already packed = rB + col)
    {
        int row = tid >> 1, half = tid & 1;
        const uint32_t* src = Ck + row*132 + half*64;
        uint32_t tk[4];
        #pragma unroll
        for (int p = 0; p < 4; p++) tk[p] = 0u;
        #pragma unroll 4
        for (int c4 = 0; c4 < 16; c4++) {
            uint4 kk = *(const uint4*)(src + c4*4);
            ins4x4(tk, kk.x, kk.y, kk.z, kk.w);
        }
        uint32_t* dst = g_cand + ((size_t)(b*SS + rA + row))*128 + (bj*2 + half)*4;
        *(uint4*)(dst) = make_uint4(tk[0], tk[1], tk[2], tk[3]);
    }

    // column scan (no rewrite): candidates for rows of tile bj; re-pack index = rA + r
    if (bi != bj) {
        int col = tid >> 1, half = tid & 1;
        int rbase = half*64;
        uint32_t tk[4];
        #pragma unroll
        for (int p = 0; p < 4; p++) tk[p] = 0u;
        const uint32_t* src = Ck + (size_t)rbase*132 + col;
        #pragma unroll 4
        for (int r4 = 0; r4 < 16; r4++) {
            uint32_t k0 = src[(r4*4+0)*132];
            uint32_t k1 = src[(r4*4+1)*132];
            uint32_t k2 = src[(r4*4+2)*132];
            uint32_t k3 = src[(r4*4+3)*132];
            int rg = rA + rbase + r4*4;
            k0 = (k0 & 0xFFFFF800u) | (uint32_t)(rg+0);
            k1 = (k1 & 0xFFFFF800u) | (uint32_t)(rg+1);
            k2 = (k2 & 0xFFFFF800u) | (uint32_t)(rg+2);
            k3 = (k3 & 0xFFFFF800u) | (uint32_t)(rg+3);
            ins4x4(tk, k0, k1, k2, k3);
        }
        uint32_t* dst = g_cand + ((size_t)(b*SS + rB + col))*128 + (bi*2 + half)*4;
        *(uint4*)(dst) = make_uint4(tk[0], tk[1], tk[2], tk[3]);
    }
}

// ---------------- 3. merge 128 keys -> top-10 -> exact rescore -> top-3 -> scatter weighted edges ----------------
// grid RR/8, 256 threads, warp per row
__global__ void __launch_bounds__(256) k_mrg() {
    __shared__ int   cand[8][NCAND];
    __shared__ float ex[8][NCAND];
    int tid = threadIdx.x;
    int lane = tid & 31, wid = tid >> 5;
    int row = blockIdx.x*8 + wid;
    int b = row / SS;
    int iloc = row - b*SS;

    const uint32_t* src = g_cand + (size_t)row*128;
    uint32_t k[4];
    #pragma unroll
    for (int p = 0; p < 4; p++) k[p] = src[p*32 + lane];   // coalesced

    for (int p = 0; p < NCAND; p++) {
        uint32_t bk = 0u;
        #pragma unroll
        for (int q = 0; q < 4; q++) bk = (k[q] > bk) ? k[q] : bk;
        #pragma unroll
        for (int o = 16; o > 0; o >>= 1) {
            uint32_t ov = __shfl_xor_sync(0xffffffffu, bk, o);
            bk = (ov > bk) ? ov : bk;
        }
        #pragma unroll
        for (int q = 0; q < 4; q++) if (k[q] == bk) k[q] = 0u;
        if (lane == 0) cand[wid][p] = (int)(bk & 0x7FFu);
    }
    __syncwarp();

    // exact fp32 rescore (self-candidates rejected)
    const float* xi = g_nrm + (size_t)row*DD;
    for (int c = 0; c < NCAND; c++) {
        int j = cand[wid][c];
        const float* xj = g_nrm + ((size_t)b*SS + j)*DD;
        float s = 0.f;
        #pragma unroll
        for (int q = 0; q < DD/32; q++) s += xi[lane + q*32] * xj[lane + q*32];
        #pragma unroll
        for (int o = 16; o > 0; o >>= 1) s += __shfl_xor_sync(0xffffffffu, s, o);
        if (lane == 0) ex[wid][c] = (j == iloc) ? NEG_INF : s;
    }
    __syncwarp();

    if (lane == 0) {
        bool used[NCAND] = {};
        for (int p = 0; p < 3; p++) {
            float bv = NEG_INF; int bc = -1;
            for (int c = 0; c < NCAND; c++) {
                if (used[c]) continue;
                if (bc < 0 || ex[wid][c] > bv) { bv = ex[wid][c]; bc = c; }
            }
            used[bc] = true;
            int j = cand[wid][bc];
            float w = ex[wid][bc];
            int pos = atomicAdd(&g_acnt[row], 1);
            if (pos < ACAP) { g_aidx[(size_t)row*ACAP + pos] = j; g_awt[(size_t)row*ACAP + pos] = w; }
            int rj = b*SS + j;
            int pos2 = atomicAdd(&g_acnt[rj], 1);
            if (pos2 < ACAP) { g_aidx[(size_t)rj*ACAP + pos2] = iloc; g_awt[(size_t)rj*ACAP + pos2] = w; }
        }
    }
}

// ---------------- 5. neighbor aggregation from weighted lists -> combined[256:512] ----------------
__global__ void k_agg(const float* __restrict__ x) {
    int row = blockIdx.x;
    int b = row / SS;
    __shared__ int   sj[ACAP];
    __shared__ float sw[ACAP];
    __shared__ int   m;
    int t = threadIdx.x;

    int n = min(g_acnt[row], ACAP);
    if (t < n) {
        sj[t] = g_aidx[(size_t)row*ACAP + t];
        sw[t] = g_awt[(size_t)row*ACAP + t];
    }
    __syncthreads();

    if (t == 0) {
        for (int a = 1; a < n; a++) {
            int j = sj[a]; float w = sw[a];
            int p = a - 1;
            while (p >= 0 && sj[p] > j) { sj[p+1] = sj[p]; sw[p+1] = sw[p]; p--; }
            sj[p+1] = j; sw[p+1] = w;
        }
        int mm = 0;
        for (int a = 0; a < n; a++) {
            if (a == 0 || sj[a] != sj[a-1]) { sj[mm] = sj[a]; sw[mm] = sw[a]; mm++; }
        }
        m = mm;
    }
    __syncthreads();
    int mm = m;

    float csum = 0.f;
    for (int l = 0; l < mm; l++) csum += sw[l];
    float acc = 0.f;
    for (int l = 0; l < mm; l++)
        acc += sw[l] * x[((size_t)b*SS + sj[l])*DD + t];
    float mval = acc / fmaxf(csum, 1.0f);
    g_cf16[(size_t)row*KF + DD + t] = __float2half(mval);
}

// ---------------- 6. projection GEMM via single fp16 HMMA, cp.async 2-stage + bias + residual ----------------
__global__ void __launch_bounds__(256, 2) k_out2(const float* __restrict__ x,
                                                 const float* __restrict__ bias) {
    extern __shared__ char smem[];
    uint32_t sb = smem_u32(smem);
    int tid = threadIdx.x;
    int lane = tid & 31, wid = tid >> 5;
    int wm = wid & 3, wn = wid >> 2;        // 4 x 2 warps, warp tile 32x32

    int bx = blockIdx.x;
    int rA = (bx >> 2) * 128, cB = (bx & 3) * 64;

    float acc[2][4][4];
    #pragma unroll
    for (int i = 0; i < 2; i++)
        #pragma unroll
        for (int j = 0; j < 4; j++)
            #pragma unroll
            for (int q = 0; q < 4; q++) acc[i][j][q] = 0.f;

    int ar = lane & 15, aseg = lane >> 4;
    int br = lane & 7, bsel = lane >> 3;
    int bnoff = (bsel >> 1) * 8, bkoff = (bsel & 1) * 8;

    int lrow = tid >> 1, lcol = (tid & 1) * 32;
    uint32_t so = (uint32_t)(lrow*LDA + lcol) * 2;

    // prologue: chunk 0 -> stage 0
    {
        const char* gA = (const char*)(g_cf16 + (size_t)(rA+lrow)*KF + lcol);
        uint32_t dA = sb + so;
        #pragma unroll
        for (int q = 0; q < 4; q++) cpa16(dA + q*16, gA + q*16);
        if (tid < 128) {
            const char* gB = (const char*)(g_wf16 + (size_t)(cB+lrow)*KF + lcol);
            uint32_t dB = sb + OUT_A_B + so;
            #pragma unroll
            for (int q = 0; q < 4; q++) cpa16(dB + q*16, gB + q*16);
        }
        CP_COMMIT();
    }

    for (int c = 0; c < KF/KC; c++) {       // 8 chunks of 64
        if (c + 1 < KF/KC) {
            int kk = (c+1) * KC;
            int s = (c+1) & 1;
            const char* gA = (const char*)(g_cf16 + (size_t)(rA+lrow)*KF + kk + lcol);
            uint32_t dA = sb + s*OUT_STAGE_B + so;
            #pragma unroll
            for (int q = 0; q < 4; q++) cpa16(dA + q*16, gA + q*16);
            if (tid < 128) {
                const char* gB = (const char*)(g_wf16 + (size_t)(cB+lrow)*KF + kk + lcol);
                uint32_t dB = sb + s*OUT_STAGE_B + OUT_A_B + so;
                #pragma unroll
                for (int q = 0; q < 4; q++) cpa16(dB + q*16, gB + q*16);
            }
            CP_COMMIT();
            CP_WAIT(1);
        } else {
            CP_WAIT(0);
        }
        __syncthreads();

        uint32_t stA = sb + (c & 1)*OUT_STAGE_B;
        uint32_t stB = stA + OUT_A_B;
        #pragma unroll
        for (int ks = 0; ks < KC/16; ks++) {
            int kb = ks * 16;
            uint32_t ah[2][4];
            #pragma unroll
            for (int mt = 0; mt < 2; mt++) {
                uint32_t ao = (uint32_t)((wm*32 + mt*16 + ar)*LDA + kb + aseg*8) * 2;
                ldmx4(ah[mt], stA + ao);
            }
            #pragma unroll
            for (int np = 0; np < 2; np++) {
                uint32_t bo = (uint32_t)((wn*32 + np*16 + bnoff + br)*LDA + kb + bkoff) * 2;
                uint32_t bh[4];
                ldmx4(bh, stB + bo);
                #pragma unroll
                for (int mt = 0; mt < 2; mt++)
                    #pragma unroll
                    for (int sub = 0; sub < 2; sub++)
                        mma16816h(acc[mt][np*2 + sub], ah[mt], bh[sub*2], bh[sub*2+1]);
            }
        }
        __syncthreads();
    }

    int fr = lane >> 2, fc = (lane & 3) * 2;
    #pragma unroll
    for (int mt = 0; mt < 2; mt++) {
        #pragma unroll
        for (int nt = 0; nt < 4; nt++) {
            int r0 = rA + wm*32 + mt*16 + fr;
            int cc = cB + wn*32 + nt*8 + fc;
            g_y[(size_t)r0*DD + cc]       = x[(size_t)r0*DD + cc]       + acc[mt][nt][0] + bias[cc];
            g_y[(size_t)r0*DD + cc+1]     = x[(size_t)r0*DD + cc+1]     + acc[mt][nt][1] + bias[cc+1];
            g_y[(size_t)(r0+8)*DD + cc]   = x[(size_t)(r0+8)*DD + cc]   + acc[mt][nt][2] + bias[cc];
            g_y[(size_t)(r0+8)*DD + cc+1] = x[(size_t)(r0+8)*DD + cc+1] + acc[mt][nt][3] + bias[cc+1];
        }
    }
}

// ---------------- 7. LayerNorm ----------------
__global__ void k_ln(const float* __restrict__ gamma, const float* __restrict__ beta,
                     float* __restrict__ out) {
    int row = blockIdx.x;
    int t = threadIdx.x;
    float v = g_y[(size_t)row*DD + t];
    __shared__ float sh[8];

    float s = v;
    #pragma unroll
    for (int o = 16; o > 0; o >>= 1) s += __shfl_xor_sync(0xffffffffu, s, o);
    if ((t & 31) == 0) sh[t >> 5] = s;
    __syncthreads();
    if (t < 32) {
        float z = (t < 8) ? sh[t] : 0.f;
        #pragma unroll
        for (int o = 4; o > 0; o >>= 1) z += __shfl_xor_sync(0xffffffffu, z, o);
        if (t == 0) sh[0] = z;
    }
    __syncthreads();
    float mu = sh[0] * (1.0f/DD);
    __syncthreads();

    float d = v - mu;
    float s2 = d*d;
    #pragma unroll
    for (int o = 16; o > 0; o >>= 1) s2 += __shfl_xor_sync(0xffffffffu, s2, o);
    if ((t & 31) == 0) sh[t >> 5] = s2;
    __syncthreads();
    if (t < 32) {
        float z = (t < 8) ? sh[t] : 0.f;
        #pragma unroll
        for (int o = 4; o > 0; o >>= 1) z += __shfl_xor_sync(0xffffffffu, z, o);
        if (t == 0) sh[0] = z;
    }
    __syncthreads();
    float var = sh[0] * (1.0f/DD);

    out[(size_t)row*DD + t] = d * rsqrtf(var + 1e-5f) * gamma[t] + beta[t];
}

// ---------------- launch ----------------
extern "C" void kernel_launch(void* const* d_in, const int* in_sizes, int n_in,
                              void* d_out, int out_size) {
    const float* x     = (const float*)d_in[0];
    const float* W     = (const float*)d_in[1];
    const float* bias  = (const float*)d_in[2];
    const float* gamma = (const float*)d_in[3];
    const float* beta  = (const float*)d_in[4];
    float* out = (float*)d_out;

    cudaFuncSetAttribute(k_sim3, cudaFuncAttributeMaxDynamicSharedMemorySize, SIM_SMEM);
    cudaFuncSetAttribute(k_out2, cudaFuncAttributeMaxDynamicSharedMemorySize, OUT_SMEM);

    k_clr<<<(RR + 255)/256, 256>>>();
    k_norm<<<RR, 256>>>(x);
    k_w16<<<(DD*KF)/256, 256>>>(W);
    k_sim3<<<dim3(TRI2, BB), 256, SIM_SMEM>>>();
    k_mrg<<<RR/8, 256>>>();
    k_agg<<<RR, 256>>>(x);
    k_out2<<<(RR/128)*4, 256, OUT_SMEM>>>(x, bias);
    k_ln<<<RR, 256>>>(gamma, beta, out);
}

// round 17
// speedup vs baseline: 1.4860x; 1.0749x over previous
#include <cuda_runtime.h>
#include <cuda_fp16.h>
#include <math.h>
#include <stdint.h>

#define BB 8
#define SS 2048
#define DD 256
#define RR (BB*SS)          // 16384 rows total
#define NEG_INF -1.0e30f

// ----- HMMA sim tiling -----
#define TS2 128
#define NT2 (SS/TS2)                 // 16
#define TRI2 (NT2*(NT2+1)/2)         // 136
#define KC 64
#define NCHUNK (DD/KC)               // 4
#define LDA 72                       // padded smem row stride (2B elems)
#define TILE_B (128*LDA*2)           // 18432 bytes per operand tile
#define SIM_STAGE_B (2*TILE_B)       // A+B per stage = 36864
#define SIM_SMEM (2*SIM_STAGE_B)     // 73728 (covers key buffer 128*132*4=67584)

#define NCAND 10                     // merge width (rescored exactly)
#define ACAP 96                      // adjacency list capacity per row

// ----- fused out+LN tiling: 64 rows x 256 cols per block -----
#define KF (2*DD)                    // 512
#define OM 64
#define OUT_A_B2 (OM*LDA*2)          // 9216
#define OUT_B_B2 (DD*LDA*2)          // 36864
#define OUT_STAGE2 (OUT_A_B2 + OUT_B_B2)   // 46080
#define YSTRIDE 260
#define OUT_SMEM2 (2*OUT_STAGE2)           // 92160 (>= OM*YSTRIDE*4 = 66560)

// ---------------- static scratch ----------------
__device__ float    g_nrm[(size_t)RR*DD];            // 16 MB exact normalized rows
__device__ __half   g_f16[(size_t)RR*DD];            // 8 MB fp16 normalized rows
__device__ uint32_t g_cand[(size_t)RR*128];          // 8.4 MB packed candidate keys
__device__ int      g_acnt[RR];                      // adjacency counts
__device__ int      g_aidx[(size_t)RR*ACAP];         // adjacency indices (batch-local)
__device__ float    g_awt[(size_t)RR*ACAP];          // adjacency weights (exact fp32)
__device__ __half   g_cf16[(size_t)RR*KF];           // 16 MB combined fp16 [x | nm]
__device__ __half   g_wf16[(size_t)DD*KF];           // 256 KB W fp16

__device__ __forceinline__ uint32_t smem_u32(const void* p) {
    uint32_t a;
    asm("{ .reg .u64 t; cvta.to.shared.u64 t, %1; cvt.u32.u64 %0, t; }" : "=r"(a) : "l"(p));
    return a;
}
__device__ __forceinline__ void ldmx4(uint32_t* r, uint32_t addr) {
    asm volatile("ldmatrix.sync.aligned.m8n8.x4.shared.b16 {%0,%1,%2,%3}, [%4];"
        : "=r"(r[0]), "=r"(r[1]), "=r"(r[2]), "=r"(r[3]) : "r"(addr));
}
__device__ __forceinline__ void mma16816h(float* c, const uint32_t* a, uint32_t b0, uint32_t b1) {
    asm volatile("mma.sync.aligned.m16n8k16.row.col.f32.f16.f16.f32 "
        "{%0,%1,%2,%3}, {%4,%5,%6,%7}, {%8,%9}, {%0,%1,%2,%3};"
        : "+f"(c[0]), "+f"(c[1]), "+f"(c[2]), "+f"(c[3])
        : "r"(a[0]), "r"(a[1]), "r"(a[2]), "r"(a[3]), "r"(b0), "r"(b1));
}
__device__ __forceinline__ void cpa16(uint32_t dst, const void* src) {
    asm volatile("cp.async.ca.shared.global [%0], [%1], 16;" :: "r"(dst), "l"(src));
}
#define CP_COMMIT() asm volatile("cp.async.commit_group;" ::: "memory")
#define CP_WAIT(n)  asm volatile("cp.async.wait_group %0;" :: "n"(n) : "memory")

// cheap monotone pack: clamp negatives to 0, keep top 21 value bits, 11-bit index low
__device__ __forceinline__ uint32_t f2key(float f, int j) {
    uint32_t u = __float_as_uint(fmaxf(f, 0.0f));
    return (u & 0xFFFFF800u) | (uint32_t)j;
}
__device__ __forceinline__ void ins4(uint32_t* tk, uint32_t k) {
    if (k > tk[3]) {
        #pragma unroll
        for (int p = 3; p >= 1; p--)
            tk[p] = (k > tk[p-1]) ? tk[p-1] : (k > tk[p] ? k : tk[p]);
        if (k > tk[0]) tk[0] = k;
    }
}
__device__ __forceinline__ void ins4x4(uint32_t* tk, uint32_t k0, uint32_t k1, uint32_t k2, uint32_t k3) {
    uint32_t m0 = k0 > k1 ? k0 : k1;
    uint32_t m1 = k2 > k3 ? k2 : k3;
    if ((m0 > m1 ? m0 : m1) > tk[3]) {
        ins4(tk, k0); ins4(tk, k1); ins4(tk, k2); ins4(tk, k3);
    }
}

// ---------------- 0. init: W -> fp16 + clear adjacency counters ----------------
__global__ void k_init(const float* __restrict__ W) {
    int t = blockIdx.x*256 + threadIdx.x;
    if (t < DD*KF) g_wf16[t] = __float2half(W[t]);
    else {
        int r = t - DD*KF;
        if (r < RR) g_acnt[r] = 0;
    }
}

// ---------------- 1. row L2-normalize -> fp32 + fp16; raw x -> combined[0:256] ----------------
__global__ void k_norm(const float* __restrict__ x) {
    int row = blockIdx.x;
    int t = threadIdx.x;
    float v = x[(size_t)row*DD + t];
    __shared__ float sh[8];
    float s = v*v;
    #pragma unroll
    for (int o = 16; o > 0; o >>= 1) s += __shfl_xor_sync(0xffffffffu, s, o);
    if ((t & 31) == 0) sh[t >> 5] = s;
    __syncthreads();
    if (t < 32) {
        float z = (t < 8) ? sh[t] : 0.f;
        #pragma unroll
        for (int o = 4; o > 0; o >>= 1) z += __shfl_xor_sync(0xffffffffu, z, o);
        if (t == 0) sh[0] = z;
    }
    __syncthreads();
    float nrm = sqrtf(sh[0]);
    float sc = 1.f / fmaxf(nrm, 1e-12f);
    float nv = v * sc;
    g_nrm[(size_t)row*DD + t] = nv;
    g_f16[(size_t)row*DD + t] = __float2half(nv);
    g_cf16[(size_t)row*KF + t] = __float2half(v);
}

// ---------------- 2. sim tiles via single fp16 HMMA, cp.async 2-stage; fused top-4 candidates ----------------
__global__ void __launch_bounds__(256, 2) k_sim3() {
    extern __shared__ char smem[];
    uint32_t sb = smem_u32(smem);
    int tid = threadIdx.x;
    int lane = tid & 31, wid = tid >> 5;
    int wm = wid & 3, wn = wid >> 2;

    int t = blockIdx.x;
    int bi = 0;
    while ((bi+1)*(bi+2)/2 <= t) bi++;
    int bj = t - bi*(bi+1)/2;           // bi >= bj
    int b = blockIdx.y;
    int rA = bi*TS2, rB = bj*TS2;

    const __half* hb = g_f16 + (size_t)b*SS*DD;

    float acc[2][8][4];
    #pragma unroll
    for (int i = 0; i < 2; i++)
        #pragma unroll
        for (int j = 0; j < 8; j++)
            #pragma unroll
            for (int q = 0; q < 4; q++) acc[i][j][q] = 0.f;

    int ar = lane & 15, aseg = lane >> 4;
    int br = lane & 7, bsel = lane >> 3;
    int bnoff = (bsel >> 1) * 8, bkoff = (bsel & 1) * 8;

    int lrow = tid >> 1, lcol = (tid & 1) * 32;
    uint32_t so = (uint32_t)(lrow*LDA + lcol) * 2;

    {
        const char* gA = (const char*)(hb + (size_t)(rA+lrow)*DD + lcol);
        const char* gB = (const char*)(hb + (size_t)(rB+lrow)*DD + lcol);
        uint32_t dA = sb + so, dB = sb + TILE_B + so;
        #pragma unroll
        for (int q = 0; q < 4; q++) { cpa16(dA + q*16, gA + q*16); cpa16(dB + q*16, gB + q*16); }
        CP_COMMIT();
    }

    for (int c = 0; c < NCHUNK; c++) {
        if (c + 1 < NCHUNK) {
            int kk = (c+1) * KC;
            int s = (c+1) & 1;
            const char* gA = (const char*)(hb + (size_t)(rA+lrow)*DD + kk + lcol);
            const char* gB = (const char*)(hb + (size_t)(rB+lrow)*DD + kk + lcol);
            uint32_t dA = sb + s*SIM_STAGE_B + so, dB = dA + TILE_B;
            #pragma unroll
            for (int q = 0; q < 4; q++) { cpa16(dA + q*16, gA + q*16); cpa16(dB + q*16, gB + q*16); }
            CP_COMMIT();
            CP_WAIT(1);
        } else {
            CP_WAIT(0);
        }
        __syncthreads();

        uint32_t stA = sb + (c & 1)*SIM_STAGE_B;
        uint32_t stB = stA + TILE_B;
        #pragma unroll
        for (int ks = 0; ks < KC/16; ks++) {
            int kb = ks * 16;
            uint32_t ah[2][4];
            #pragma unroll
            for (int mt = 0; mt < 2; mt++) {
                uint32_t ao = (uint32_t)((wm*32 + mt*16 + ar)*LDA + kb + aseg*8) * 2;
                ldmx4(ah[mt], stA + ao);
            }
            #pragma unroll
            for (int np = 0; np < 4; np++) {
                uint32_t bo = (uint32_t)((wn*64 + np*16 + bnoff + br)*LDA + kb + bkoff) * 2;
                uint32_t bh[4];
                ldmx4(bh, stB + bo);
                #pragma unroll
                for (int mt = 0; mt < 2; mt++)
                    #pragma unroll
                    for (int sub = 0; sub < 2; sub++)
                        mma16816h(acc[mt][np*2 + sub], ah[mt], bh[sub*2], bh[sub*2+1]);
            }
        }
        __syncthreads();
    }

    // -------- epilogue: single key write, row scan + in-place column scan, top-4 each --------
    uint32_t* Ck = (uint32_t*)smem;     // [128][132], key = (val21 | col11)
    int fr = lane >> 2, fc = (lane & 3) * 2;

    #pragma unroll
    for (int mt = 0; mt < 2; mt++) {
        #pragma unroll
        for (int nt = 0; nt < 8; nt++) {
            int r0 = wm*32 + mt*16 + fr;
            int cc = wn*64 + nt*8 + fc;
            int g0 = rA + r0, g1 = rA + r0 + 8;
            int j0 = rB + cc, j1 = rB + cc + 1;
            Ck[r0*132 + cc]       = (g0 == j0) ? 0u : f2key(acc[mt][nt][0], j0);
            Ck[r0*132 + cc+1]     = (g0 == j1) ? 0u : f2key(acc[mt][nt][1], j1);
            Ck[(r0+8)*132 + cc]   = (g1 == j0) ? 0u : f2key(acc[mt][nt][2], j0);
            Ck[(r0+8)*132 + cc+1] = (g1 == j1) ? 0u : f2key(acc[mt][nt][3], j1);
        }
    }
    __syncthreads();

    {
        int row = tid >> 1, half = tid & 1;
        const uint32_t* src = Ck + row*132 + half*64;
        uint32_t tk[4];
        #pragma unroll
        for (int p = 0; p < 4; p++) tk[p] = 0u;
        #pragma unroll 4
        for (int c4 = 0; c4 < 16; c4++) {
            uint4 kk = *(const uint4*)(src + c4*4);
            ins4x4(tk, kk.x, kk.y, kk.z, kk.w);
        }
        uint32_t* dst = g_cand + ((size_t)(b*SS + rA + row))*128 + (bj*2 + half)*4;
        *(uint4*)(dst) = make_uint4(tk[0], tk[1], tk[2], tk[3]);
    }

    if (bi != bj) {
        int col = tid >> 1, half = tid & 1;
        int rbase = half*64;
        uint32_t tk[4];
        #pragma unroll
        for (int p = 0; p < 4; p++) tk[p] = 0u;
        const uint32_t* src = Ck + (size_t)rbase*132 + col;
        #pragma unroll 4
        for (int r4 = 0; r4 < 16; r4++) {
            uint32_t k0 = src[(r4*4+0)*132];
            uint32_t k1 = src[(r4*4+1)*132];
            uint32_t k2 = src[(r4*4+2)*132];
            uint32_t k3 = src[(r4*4+3)*132];
            int rg = rA + rbase + r4*4;
            k0 = (k0 & 0xFFFFF800u) | (uint32_t)(rg+0);
            k1 = (k1 & 0xFFFFF800u) | (uint32_t)(rg+1);
            k2 = (k2 & 0xFFFFF800u) | (uint32_t)(rg+2);
            k3 = (k3 & 0xFFFFF800u) | (uint32_t)(rg+3);
            ins4x4(tk, k0, k1, k2, k3);
        }
        uint32_t* dst = g_cand + ((size_t)(b*SS + rB + col))*128 + (bi*2 + half)*4;
        *(uint4*)(dst) = make_uint4(tk[0], tk[1], tk[2], tk[3]);
    }
}

// ---------------- 3. merge 128 keys -> top-10 -> exact rescore -> top-3 -> scatter weighted edges ----------------
__global__ void __launch_bounds__(256) k_mrg() {
    __shared__ int   cand[8][NCAND];
    __shared__ float ex[8][NCAND];
    int tid = threadIdx.x;
    int lane = tid & 31, wid = tid >> 5;
    int row = blockIdx.x*8 + wid;
    int b = row / SS;
    int iloc = row - b*SS;

    const uint32_t* src = g_cand + (size_t)row*128;
    uint32_t k[4];
    #pragma unroll
    for (int p = 0; p < 4; p++) k[p] = src[p*32 + lane];

    for (int p = 0; p < NCAND; p++) {
        uint32_t bk = 0u;
        #pragma unroll
        for (int q = 0; q < 4; q++) bk = (k[q] > bk) ? k[q] : bk;
        #pragma unroll
        for (int o = 16; o > 0; o >>= 1) {
            uint32_t ov = __shfl_xor_sync(0xffffffffu, bk, o);
            bk = (ov > bk) ? ov : bk;
        }
        #pragma unroll
        for (int q = 0; q < 4; q++) if (k[q] == bk) k[q] = 0u;
        if (lane == 0) cand[wid][p] = (int)(bk & 0x7FFu);
    }
    __syncwarp();

    const float* xi = g_nrm + (size_t)row*DD;
    for (int c = 0; c < NCAND; c++) {
        int j = cand[wid][c];
        const float* xj = g_nrm + ((size_t)b*SS + j)*DD;
        float s = 0.f;
        #pragma unroll
        for (int q = 0; q < DD/32; q++) s += xi[lane + q*32] * xj[lane + q*32];
        #pragma unroll
        for (int o = 16; o > 0; o >>= 1) s += __shfl_xor_sync(0xffffffffu, s, o);
        if (lane == 0) ex[wid][c] = (j == iloc) ? NEG_INF : s;
    }
    __syncwarp();

    if (lane == 0) {
        bool used[NCAND] = {};
        for (int p = 0; p < 3; p++) {
            float bv = NEG_INF; int bc = -1;
            for (int c = 0; c < NCAND; c++) {
                if (used[c]) continue;
                if (bc < 0 || ex[wid][c] > bv) { bv = ex[wid][c]; bc = c; }
            }
            used[bc] = true;
            int j = cand[wid][bc];
            float w = ex[wid][bc];
            int pos = atomicAdd(&g_acnt[row], 1);
            if (pos < ACAP) { g_aidx[(size_t)row*ACAP + pos] = j; g_awt[(size_t)row*ACAP + pos] = w; }
            int rj = b*SS + j;
            int pos2 = atomicAdd(&g_acnt[rj], 1);
            if (pos2 < ACAP) { g_aidx[(size_t)rj*ACAP + pos2] = iloc; g_awt[(size_t)rj*ACAP + pos2] = w; }
        }
    }
}

// ---------------- 5. neighbor aggregation from weighted lists -> combined[256:512] ----------------
__global__ void k_agg(const float* __restrict__ x) {
    int row = blockIdx.x;
    int b = row / SS;
    __shared__ int   sj[ACAP];
    __shared__ float sw[ACAP];
    __shared__ int   m;
    int t = threadIdx.x;

    int n = min(g_acnt[row], ACAP);
    if (t < n) {
        sj[t] = g_aidx[(size_t)row*ACAP + t];
        sw[t] = g_awt[(size_t)row*ACAP + t];
    }
    __syncthreads();

    if (t == 0) {
        for (int a = 1; a < n; a++) {
            int j = sj[a]; float w = sw[a];
            int p = a - 1;
            while (p >= 0 && sj[p] > j) { sj[p+1] = sj[p]; sw[p+1] = sw[p]; p--; }
            sj[p+1] = j; sw[p+1] = w;
        }
        int mm = 0;
        for (int a = 0; a < n; a++) {
            if (a == 0 || sj[a] != sj[a-1]) { sj[mm] = sj[a]; sw[mm] = sw[a]; mm++; }
        }
        m = mm;
    }
    __syncthreads();
    int mm = m;

    float csum = 0.f;
    for (int l = 0; l < mm; l++) csum += sw[l];
    float acc = 0.f;
    for (int l = 0; l < mm; l++)
        acc += sw[l] * x[((size_t)b*SS + sj[l])*DD + t];
    float mval = acc / fmaxf(csum, 1.0f);
    g_cf16[(size_t)row*KF + DD + t] = __float2half(mval);
}

// ---------------- 6. fused projection GEMM (fp16) + bias + residual + LayerNorm ----------------
// grid RR/64 blocks, tile 64 rows x 256 cols, 8 warps (2x4)
__global__ void __launch_bounds__(256, 2) k_out3(const float* __restrict__ x,
                                                 const float* __restrict__ bias,
                                                 const float* __restrict__ gamma,
                                                 const float* __restrict__ beta,
                                                 float* __restrict__ out) {
    extern __shared__ char smem[];
    uint32_t sb = smem_u32(smem);
    int tid = threadIdx.x;
    int lane = tid & 31, wid = tid >> 5;
    int wm = wid & 1, wn = wid >> 1;        // 2 x 4 warps, warp tile 32x64

    int rA = blockIdx.x * OM;

    float acc[2][8][4];
    #pragma unroll
    for (int i = 0; i < 2; i++)
        #pragma unroll
        for (int j = 0; j < 8; j++)
            #pragma unroll
            for (int q = 0; q < 4; q++) acc[i][j][q] = 0.f;

    int ar = lane & 15, aseg = lane >> 4;
    int br = lane & 7, bsel = lane >> 3;
    int bnoff = (bsel >> 1) * 8, bkoff = (bsel & 1) * 8;

    // loaders: A = 64 rows x 64k (tid>>2 row, (tid&3)*16 col, 32B each);
    //          B = 256 rows x 64k (tid row, full 128B each)
    int arow = tid >> 2, acol = (tid & 3) * 16;
    uint32_t soA = (uint32_t)(arow*LDA + acol) * 2;
    uint32_t soB = (uint32_t)(tid*LDA) * 2;

    {
        const char* gA = (const char*)(g_cf16 + (size_t)(rA+arow)*KF + acol);
        const char* gB = (const char*)(g_wf16 + (size_t)tid*KF);
        uint32_t dA = sb + soA, dB = sb + OUT_A_B2 + soB;
        #pragma unroll
        for (int q = 0; q < 2; q++) cpa16(dA + q*16, gA + q*16);
        #pragma unroll
        for (int q = 0; q < 8; q++) cpa16(dB + q*16, gB + q*16);
        CP_COMMIT();
    }

    for (int c = 0; c < KF/KC; c++) {
        if (c + 1 < KF/KC) {
            int kk = (c+1) * KC;
            int s = (c+1) & 1;
            const char* gA = (const char*)(g_cf16 + (size_t)(rA+arow)*KF + kk + acol);
            const char* gB = (const char*)(g_wf16 + (size_t)tid*KF + kk);
            uint32_t dA = sb + s*OUT_STAGE2 + soA, dB = sb + s*OUT_STAGE2 + OUT_A_B2 + soB;
            #pragma unroll
            for (int q = 0; q < 2; q++) cpa16(dA + q*16, gA + q*16);
            #pragma unroll
            for (int q = 0; q < 8; q++) cpa16(dB + q*16, gB + q*16);
            CP_COMMIT();
            CP_WAIT(1);
        } else {
            CP_WAIT(0);
        }
        __syncthreads();

        uint32_t stA = sb + (c & 1)*OUT_STAGE2;
        uint32_t stB = stA + OUT_A_B2;
        #pragma unroll
        for (int ks = 0; ks < KC/16; ks++) {
            int kb = ks * 16;
            uint32_t ah[2][4];
            #pragma unroll
            for (int mt = 0; mt < 2; mt++) {
                uint32_t ao = (uint32_t)((wm*32 + mt*16 + ar)*LDA + kb + aseg*8) * 2;
                ldmx4(ah[mt], stA + ao);
            }
            #pragma unroll
            for (int np = 0; np < 4; np++) {
                uint32_t bo = (uint32_t)((wn*64 + np*16 + bnoff + br)*LDA + kb + bkoff) * 2;
                uint32_t bh[4];
                ldmx4(bh, stB + bo);
                #pragma unroll
                for (int mt = 0; mt < 2; mt++)
                    #pragma unroll
                    for (int sub = 0; sub < 2; sub++)
                        mma16816h(acc[mt][np*2 + sub], ah[mt], bh[sub*2], bh[sub*2+1]);
            }
        }
        __syncthreads();
    }

    // -------- epilogue: y = x + acc + bias into smem, then per-row LayerNorm --------
    float* Y = (float*)smem;   // [64][YSTRIDE]
    int fr = lane >> 2, fc = (lane & 3) * 2;
    #pragma unroll
    for (int mt = 0; mt < 2; mt++) {
        #pragma unroll
        for (int nt = 0; nt < 8; nt++) {
            int r0 = wm*32 + mt*16 + fr;
            int cc = wn*64 + nt*8 + fc;
            int gr0 = rA + r0, gr1 = rA + r0 + 8;
            Y[r0*YSTRIDE + cc]       = x[(size_t)gr0*DD + cc]   + acc[mt][nt][0] + bias[cc];
            Y[r0*YSTRIDE + cc+1]     = x[(size_t)gr0*DD + cc+1] + acc[mt][nt][1] + bias[cc+1];
            Y[(r0+8)*YSTRIDE + cc]   = x[(size_t)gr1*DD + cc]   + acc[mt][nt][2] + bias[cc];
            Y[(r0+8)*YSTRIDE + cc+1] = x[(size_t)gr1*DD + cc+1] + acc[mt][nt][3] + bias[cc+1];
        }
    }
    __syncthreads();

    // each warp LNs 8 rows
    for (int r = 0; r < 8; r++) {
        int row = wid*8 + r;
        float v[8];
        float s = 0.f;
        #pragma unroll
        for (int q = 0; q < 8; q++) {
            v[q] = Y[row*YSTRIDE + lane + q*32];
            s += v[q];
        }
        #pragma unroll
        for (int o = 16; o > 0; o >>= 1) s += __shfl_xor_sync(0xffffffffu, s, o);
        float mu = s * (1.0f/DD);
        float s2 = 0.f;
        #pragma unroll
        for (int q = 0; q < 8; q++) {
            float d = v[q] - mu;
            s2 += d*d;
        }
        #pragma unroll
        for (int o = 16; o > 0; o >>= 1) s2 += __shfl_xor_sync(0xffffffffu, s2, o);
        float rstd = rsqrtf(s2 * (1.0f/DD) + 1e-5f);
        float* orow = out + (size_t)(rA + row)*DD;
        #pragma unroll
        for (int q = 0; q < 8; q++) {
            int cc = lane + q*32;
            orow[cc] = (v[q] - mu) * rstd * gamma[cc] + beta[cc];
        }
    }
}

// ---------------- launch ----------------
extern "C" void kernel_launch(void* const* d_in, const int* in_sizes, int n_in,
                              void* d_out, int out_size) {
    const float* x     = (const float*)d_in[0];
    const float* W     = (const float*)d_in[1];
    const float* bias  = (const float*)d_in[2];
    const float* gamma = (const float*)d_in[3];
    const float* beta  = (const float*)d_in[4];
    float* out = (float*)d_out;

    cudaFuncSetAttribute(k_sim3, cudaFuncAttributeMaxDynamicSharedMemorySize, SIM_SMEM);
    cudaFuncSetAttribute(k_out3, cudaFuncAttributeMaxDynamicSharedMemorySize, OUT_SMEM2);

    k_init<<<(DD*KF + RR + 255)/256, 256>>>(W);
    k_norm<<<RR, 256>>>(x);
    k_sim3<<<dim3(TRI2, BB), 256, SIM_SMEM>>>();
    k_mrg<<<RR/8, 256>>>();
    k_agg<<<RR, 256>>>(x);
    k_out3<<<RR/OM, 256, OUT_SMEM2>>>(x, bias, gamma, beta, out);
}